// round 1
// baseline (speedup 1.0000x reference)
#include <cuda_runtime.h>

#define NB 16
#define NN 32768          // nodes = 128*256 torus
#define HH 64
#define NDOUT 128
#define MROWS (NB*NN)     // 524288
#define EPSBN 1e-5f

// ---------------- scratch (feature-major layout: [b][f][n]) ----------------
__device__ float g_h[NB*HH*NN];     // 134 MB
__device__ float g_agg[NB*HH*NN];   // 134 MB
__device__ float g_y[NB*HH*NN];     // 134 MB (y1 then y2 in-place)
__device__ float g_stats[6][2*HH];  // per-use sum / sumsq
__device__ float g_scale[6][HH];
__device__ float g_shift[6][HH];
__device__ float g_pool[NB*HH];

// ---------------- zero small accumulators (once per launch) ----------------
__global__ void zero_kernel() {
    int tid = threadIdx.x;
    float* s = &g_stats[0][0];
    for (int i = tid; i < 6 * 2 * HH; i += 256) s[i] = 0.f;
    for (int i = tid; i < NB * HH; i += 256) g_pool[i] = 0.f;
}

// ---------------- embedding: h[b][f][n] = relu(sum_c x[b][c][n] W[c][f] + b[f])
__global__ void embed_kernel(const float* __restrict__ x,
                             const float* __restrict__ W,
                             const float* __restrict__ bias) {
    int b = blockIdx.z, f = blockIdx.y;
    float w0 = W[f], w1 = W[HH + f], w2 = W[2 * HH + f], bb = bias[f];
    const float4* x0 = (const float4*)(x + (size_t)(b * 3 + 0) * NN);
    const float4* x1 = (const float4*)(x + (size_t)(b * 3 + 1) * NN);
    const float4* x2 = (const float4*)(x + (size_t)(b * 3 + 2) * NN);
    float4* hp = (float4*)(g_h + (size_t)(b * HH + f) * NN);
#pragma unroll
    for (int i = 0; i < 4; i++) {
        int idx = blockIdx.x * 1024 + threadIdx.x + i * 256;
        float4 a = x0[idx], c = x1[idx], d = x2[idx];
        float4 r;
        r.x = fmaxf(fmaf(a.x, w0, fmaf(c.x, w1, fmaf(d.x, w2, bb))), 0.f);
        r.y = fmaxf(fmaf(a.y, w0, fmaf(c.y, w1, fmaf(d.y, w2, bb))), 0.f);
        r.z = fmaxf(fmaf(a.z, w0, fmaf(c.z, w1, fmaf(d.z, w2, bb))), 0.f);
        r.w = fmaxf(fmaf(a.w, w0, fmaf(c.w, w1, fmaf(d.w, w2, bb))), 0.f);
        hp[idx] = r;
    }
}

// ---------------- 4-neighbor torus stencil: agg = 0.25 * sum(neighbors) ----
__global__ void agg_kernel() {
    int b = blockIdx.z, f = blockIdx.y;
    const float* __restrict__ hp = g_h + (size_t)(b * HH + f) * NN;
    float* __restrict__ ap = g_agg + (size_t)(b * HH + f) * NN;
#pragma unroll
    for (int i = 0; i < 4; i++) {
        int n = blockIdx.x * 1024 + threadIdx.x + i * 256;
        int up = (n + 256) & 32767;
        int dn = (n + 32512) & 32767;
        int base = n & ~255, z = n & 255;
        int rt = base | ((z + 1) & 255);
        int lf = base | ((z - 1) & 255);
        ap[n] = 0.25f * (hp[up] + hp[dn] + hp[rt] + hp[lf]);
    }
}

// ---------------- GEMM1: y1 = [h | agg] @ W1 + b1, accumulate BN stats -----
// A is (M=524288, K=128) virtual: k<64 from h, k>=64 from agg. N=64 out feats.
__global__ __launch_bounds__(256) void gemm1_kernel(const float* __restrict__ W,
                                                    const float* __restrict__ bias,
                                                    int useOut) {
    __shared__ __align__(16) float As[16][256];
    __shared__ __align__(16) float Ws[16][64];
    __shared__ float red[2 * HH];
    int tid = threadIdx.x;
    int b = blockIdx.y;
    int n0 = blockIdx.x * 256;
    int tc = tid & 7, tr = tid >> 3;

    float acc[8][8];
#pragma unroll
    for (int j = 0; j < 8; j++) {
        float bv = bias[tc * 8 + j];
#pragma unroll
        for (int i = 0; i < 8; i++) acc[j][i] = bv;
    }

    for (int ch = 0; ch < 8; ch++) {
        int kc0 = ch * 16;
#pragma unroll
        for (int i = 0; i < 4; i++) {
            int idx = tid + i * 256;
            int k = idx >> 6, c = idx & 63;
            int kg = kc0 + k;
            const float* src = (kg < HH) ? (g_h + (size_t)(b * HH + kg) * NN + n0)
                                         : (g_agg + (size_t)(b * HH + kg - HH) * NN + n0);
            ((float4*)As[k])[c] = ((const float4*)src)[c];
            Ws[k][c] = W[kg * HH + c];
        }
        __syncthreads();
#pragma unroll
        for (int k = 0; k < 16; k++) {
            float4 a0 = *(const float4*)&As[k][tr * 8];
            float4 a1 = *(const float4*)&As[k][tr * 8 + 4];
            float4 w0 = *(const float4*)&Ws[k][tc * 8];
            float4 w1 = *(const float4*)&Ws[k][tc * 8 + 4];
            float av[8] = {a0.x, a0.y, a0.z, a0.w, a1.x, a1.y, a1.z, a1.w};
            float wv[8] = {w0.x, w0.y, w0.z, w0.w, w1.x, w1.y, w1.z, w1.w};
#pragma unroll
            for (int j = 0; j < 8; j++)
#pragma unroll
                for (int i = 0; i < 8; i++)
                    acc[j][i] = fmaf(wv[j], av[i], acc[j][i]);
        }
        __syncthreads();
    }

    if (tid < 2 * HH) red[tid] = 0.f;
    __syncthreads();
#pragma unroll
    for (int j = 0; j < 8; j++) {
        int f = tc * 8 + j;
        float* dst = g_y + (size_t)(b * HH + f) * NN + n0 + tr * 8;
        *(float4*)dst = make_float4(acc[j][0], acc[j][1], acc[j][2], acc[j][3]);
        *(float4*)(dst + 4) = make_float4(acc[j][4], acc[j][5], acc[j][6], acc[j][7]);
        float s = 0.f, q = 0.f;
#pragma unroll
        for (int i = 0; i < 8; i++) { s += acc[j][i]; q += acc[j][i] * acc[j][i]; }
        atomicAdd(&red[f], s);
        atomicAdd(&red[HH + f], q);
    }
    __syncthreads();
    if (tid < 2 * HH) atomicAdd(&g_stats[useOut][tid], red[tid]);
}

// ---------------- BN finalize: scale/shift per feature ---------------------
__global__ void norm_kernel(int use, const float* __restrict__ g,
                            const float* __restrict__ be) {
    int f = threadIdx.x;
    const float invM = 1.f / (float)MROWS;
    float s = g_stats[use][f], q = g_stats[use][HH + f];
    float m = s * invM;
    float v = q * invM - m * m;
    float r = rsqrtf(v + EPSBN);
    float sc = g[f] * r;
    g_scale[use][f] = sc;
    g_shift[use][f] = fmaf(-m, sc, be[f]);
}

// ---------------- GEMM2: y2 = relu(bn(y1)) @ W2 + b2 (in-place on g_y) -----
__global__ __launch_bounds__(256) void gemm2_kernel(const float* __restrict__ W,
                                                    const float* __restrict__ bias,
                                                    int useIn, int useOut) {
    __shared__ __align__(16) float As[16][256];
    __shared__ __align__(16) float Ws[16][64];
    __shared__ float red[2 * HH];
    int tid = threadIdx.x;
    int b = blockIdx.y;
    int n0 = blockIdx.x * 256;
    int tc = tid & 7, tr = tid >> 3;

    float acc[8][8];
#pragma unroll
    for (int j = 0; j < 8; j++) {
        float bv = bias[tc * 8 + j];
#pragma unroll
        for (int i = 0; i < 8; i++) acc[j][i] = bv;
    }

    for (int ch = 0; ch < 4; ch++) {
        int kc0 = ch * 16;
#pragma unroll
        for (int i = 0; i < 4; i++) {
            int idx = tid + i * 256;
            int k = idx >> 6, c = idx & 63;
            int kg = kc0 + k;
            float sc = g_scale[useIn][kg], sh = g_shift[useIn][kg];
            float4 v = ((const float4*)(g_y + (size_t)(b * HH + kg) * NN + n0))[c];
            v.x = fmaxf(fmaf(v.x, sc, sh), 0.f);
            v.y = fmaxf(fmaf(v.y, sc, sh), 0.f);
            v.z = fmaxf(fmaf(v.z, sc, sh), 0.f);
            v.w = fmaxf(fmaf(v.w, sc, sh), 0.f);
            ((float4*)As[k])[c] = v;
            Ws[k][c] = W[kg * HH + c];
        }
        __syncthreads();
#pragma unroll
        for (int k = 0; k < 16; k++) {
            float4 a0 = *(const float4*)&As[k][tr * 8];
            float4 a1 = *(const float4*)&As[k][tr * 8 + 4];
            float4 w0 = *(const float4*)&Ws[k][tc * 8];
            float4 w1 = *(const float4*)&Ws[k][tc * 8 + 4];
            float av[8] = {a0.x, a0.y, a0.z, a0.w, a1.x, a1.y, a1.z, a1.w};
            float wv[8] = {w0.x, w0.y, w0.z, w0.w, w1.x, w1.y, w1.z, w1.w};
#pragma unroll
            for (int j = 0; j < 8; j++)
#pragma unroll
                for (int i = 0; i < 8; i++)
                    acc[j][i] = fmaf(wv[j], av[i], acc[j][i]);
        }
        __syncthreads();
    }

    if (tid < 2 * HH) red[tid] = 0.f;
    __syncthreads();
#pragma unroll
    for (int j = 0; j < 8; j++) {
        int f = tc * 8 + j;
        float* dst = g_y + (size_t)(b * HH + f) * NN + n0 + tr * 8;  // in-place: all reads done
        *(float4*)dst = make_float4(acc[j][0], acc[j][1], acc[j][2], acc[j][3]);
        *(float4*)(dst + 4) = make_float4(acc[j][4], acc[j][5], acc[j][6], acc[j][7]);
        float s = 0.f, q = 0.f;
#pragma unroll
        for (int i = 0; i < 8; i++) { s += acc[j][i]; q += acc[j][i] * acc[j][i]; }
        atomicAdd(&red[f], s);
        atomicAdd(&red[HH + f], q);
    }
    __syncthreads();
    if (tid < 2 * HH) atomicAdd(&g_stats[useOut][tid], red[tid]);
}

// ---------------- h += relu(bn(y2)); optional node-mean pooling ------------
__global__ void relu_res_kernel(int use, int do_pool) {
    int b = blockIdx.z, f = blockIdx.y;
    float sc = g_scale[use][f], sh = g_shift[use][f];
    int base4 = (int)(((size_t)(b * HH + f) * NN + (size_t)blockIdx.x * 8192) >> 2);
    float4* hp = (float4*)g_h;
    const float4* yp = (const float4*)g_y;
    float ps = 0.f;
#pragma unroll
    for (int i = 0; i < 8; i++) {
        int o = base4 + threadIdx.x + i * 256;
        float4 y = yp[o];
        float4 h = hp[o];
        h.x += fmaxf(fmaf(y.x, sc, sh), 0.f);
        h.y += fmaxf(fmaf(y.y, sc, sh), 0.f);
        h.z += fmaxf(fmaf(y.z, sc, sh), 0.f);
        h.w += fmaxf(fmaf(y.w, sc, sh), 0.f);
        hp[o] = h;
        ps += h.x + h.y + h.z + h.w;
    }
    if (do_pool) {
#pragma unroll
        for (int off = 16; off; off >>= 1) ps += __shfl_down_sync(0xffffffffu, ps, off);
        __shared__ float wsum[8];
        if ((threadIdx.x & 31) == 0) wsum[threadIdx.x >> 5] = ps;
        __syncthreads();
        if (threadIdx.x == 0) {
            float t = 0.f;
#pragma unroll
            for (int w = 0; w < 8; w++) t += wsum[w];
            atomicAdd(&g_pool[b * HH + f], t);
        }
    }
}

// ---------------- head MLP: (16,64) -> relu -> (16,128) --------------------
__global__ void head_kernel(const float* __restrict__ W1, const float* __restrict__ b1,
                            const float* __restrict__ W2, const float* __restrict__ b2,
                            float* __restrict__ out) {
    __shared__ float z[NB * HH];
    int tid = threadIdx.x;
    const float invN = 1.f / (float)NN;
    for (int idx = tid; idx < NB * HH; idx += 256) {
        int b = idx >> 6, j = idx & 63;
        float acc = b1[j];
#pragma unroll
        for (int k = 0; k < HH; k++)
            acc = fmaf(g_pool[b * HH + k] * invN, W1[k * HH + j], acc);
        z[idx] = fmaxf(acc, 0.f);
    }
    __syncthreads();
    for (int idx = tid; idx < NB * NDOUT; idx += 256) {
        int b = idx >> 7, o = idx & 127;
        float acc = b2[o];
#pragma unroll
        for (int j = 0; j < HH; j++)
            acc = fmaf(z[b * HH + j], W2[j * NDOUT + o], acc);
        out[idx] = acc;
    }
}

// ---------------- driver ---------------------------------------------------
extern "C" void kernel_launch(void* const* d_in, const int* in_sizes, int n_in,
                              void* d_out, int out_size) {
    const float* x    = (const float*)d_in[0];
    // d_in[1] = edge_index (int32) — fixed 4-neighbor torus, computed analytically
    const float* embW = (const float*)d_in[2];
    const float* embB = (const float*)d_in[3];
    const float* W1   = (const float*)d_in[4];
    const float* b1   = (const float*)d_in[5];
    const float* g1   = (const float*)d_in[6];
    const float* be1  = (const float*)d_in[7];
    const float* W2   = (const float*)d_in[8];
    const float* b2   = (const float*)d_in[9];
    const float* g2   = (const float*)d_in[10];
    const float* be2  = (const float*)d_in[11];
    const float* hW1  = (const float*)d_in[12];
    const float* hb1  = (const float*)d_in[13];
    const float* hW2  = (const float*)d_in[14];
    const float* hb2  = (const float*)d_in[15];
    float* out = (float*)d_out;

    zero_kernel<<<1, 256>>>();
    embed_kernel<<<dim3(8, HH, NB), 256>>>(x, embW, embB);
    for (int l = 0; l < 3; l++) {
        agg_kernel<<<dim3(32, HH, NB), 256>>>();
        gemm1_kernel<<<dim3(128, NB), 256>>>(W1 + l * 2 * HH * HH, b1 + l * HH, l * 2);
        norm_kernel<<<1, 64>>>(l * 2, g1 + l * HH, be1 + l * HH);
        gemm2_kernel<<<dim3(128, NB), 256>>>(W2 + l * HH * HH, b2 + l * HH, l * 2, l * 2 + 1);
        norm_kernel<<<1, 64>>>(l * 2 + 1, g2 + l * HH, be2 + l * HH);
        relu_res_kernel<<<dim3(4, HH, NB), 256>>>(l * 2 + 1, (l == 2) ? 1 : 0);
    }
    head_kernel<<<1, 256>>>(hW1, hb1, hW2, hb2, out);
}

// round 6
// speedup vs baseline: 1.6171x; 1.6171x over previous
#include <cuda_runtime.h>
#include <cstdint>

#define NB 16
#define NN 32768          // nodes = 128*256 torus
#define HH 64
#define NDOUT 128
#define MROWS (NB*NN)     // 524288
#define EPSBN 1e-5f

// ---------------- scratch (feature-major layout: [b][f][n]) ----------------
__device__ float g_h[NB*HH*NN];
__device__ float g_agg[NB*HH*NN];
__device__ float g_y[NB*HH*NN];
__device__ float g_stats[6][2*HH];
__device__ float g_scale[6][HH];
__device__ float g_shift[6][HH];
__device__ float g_pool[NB*HH];

// ---------------- helpers ---------------------------------------------------
__device__ __forceinline__ uint32_t f2tf32(float x) {
    uint32_t r;
    asm("cvt.rna.tf32.f32 %0, %1;" : "=r"(r) : "f"(x));
    return r;
}
__device__ __forceinline__ void mma_tf32(float* d, const uint32_t* a, const uint32_t* b) {
    asm volatile(
        "mma.sync.aligned.m16n8k8.row.col.f32.tf32.tf32.f32 "
        "{%0,%1,%2,%3}, {%4,%5,%6,%7}, {%8,%9}, {%0,%1,%2,%3};"
        : "+f"(d[0]), "+f"(d[1]), "+f"(d[2]), "+f"(d[3])
        : "r"(a[0]), "r"(a[1]), "r"(a[2]), "r"(a[3]), "r"(b[0]), "r"(b[1]));
}

// ---------------- small kernels (unchanged from passing R1 baseline) --------
__global__ void zero_kernel() {
    int tid = threadIdx.x;
    float* s = &g_stats[0][0];
    for (int i = tid; i < 6 * 2 * HH; i += 256) s[i] = 0.f;
    for (int i = tid; i < NB * HH; i += 256) g_pool[i] = 0.f;
}

__global__ void embed_kernel(const float* __restrict__ x,
                             const float* __restrict__ W,
                             const float* __restrict__ bias) {
    int b = blockIdx.z, f = blockIdx.y;
    float w0 = W[f], w1 = W[HH + f], w2 = W[2 * HH + f], bb = bias[f];
    const float4* x0 = (const float4*)(x + (size_t)(b * 3 + 0) * NN);
    const float4* x1 = (const float4*)(x + (size_t)(b * 3 + 1) * NN);
    const float4* x2 = (const float4*)(x + (size_t)(b * 3 + 2) * NN);
    float4* hp = (float4*)(g_h + (size_t)(b * HH + f) * NN);
#pragma unroll
    for (int i = 0; i < 4; i++) {
        int idx = blockIdx.x * 1024 + threadIdx.x + i * 256;
        float4 a = x0[idx], c = x1[idx], d = x2[idx];
        float4 r;
        r.x = fmaxf(fmaf(a.x, w0, fmaf(c.x, w1, fmaf(d.x, w2, bb))), 0.f);
        r.y = fmaxf(fmaf(a.y, w0, fmaf(c.y, w1, fmaf(d.y, w2, bb))), 0.f);
        r.z = fmaxf(fmaf(a.z, w0, fmaf(c.z, w1, fmaf(d.z, w2, bb))), 0.f);
        r.w = fmaxf(fmaf(a.w, w0, fmaf(c.w, w1, fmaf(d.w, w2, bb))), 0.f);
        hp[idx] = r;
    }
}

__global__ void agg_kernel() {
    int b = blockIdx.z, f = blockIdx.y;
    const float* __restrict__ hp = g_h + (size_t)(b * HH + f) * NN;
    float* __restrict__ ap = g_agg + (size_t)(b * HH + f) * NN;
#pragma unroll
    for (int i = 0; i < 4; i++) {
        int n = blockIdx.x * 1024 + threadIdx.x + i * 256;
        int up = (n + 256) & 32767;
        int dn = (n + 32512) & 32767;
        int base = n & ~255, z = n & 255;
        int rt = base | ((z + 1) & 255);
        int lf = base | ((z - 1) & 255);
        ap[n] = 0.25f * (hp[up] + hp[dn] + hp[rt] + hp[lf]);
    }
}

__global__ void norm_kernel(int use, const float* __restrict__ g,
                            const float* __restrict__ be) {
    int f = threadIdx.x;
    const float invM = 1.f / (float)MROWS;
    float s = g_stats[use][f], q = g_stats[use][HH + f];
    float m = s * invM;
    float v = q * invM - m * m;
    float r = rsqrtf(v + EPSBN);
    float sc = g[f] * r;
    g_scale[use][f] = sc;
    g_shift[use][f] = fmaf(-m, sc, be[f]);
}

__global__ void relu_res_kernel(int use, int do_pool) {
    int b = blockIdx.z, f = blockIdx.y;
    float sc = g_scale[use][f], sh = g_shift[use][f];
    int base4 = (int)(((size_t)(b * HH + f) * NN + (size_t)blockIdx.x * 8192) >> 2);
    float4* hp = (float4*)g_h;
    const float4* yp = (const float4*)g_y;
    float ps = 0.f;
#pragma unroll
    for (int i = 0; i < 8; i++) {
        int o = base4 + threadIdx.x + i * 256;
        float4 y = yp[o];
        float4 h = hp[o];
        h.x += fmaxf(fmaf(y.x, sc, sh), 0.f);
        h.y += fmaxf(fmaf(y.y, sc, sh), 0.f);
        h.z += fmaxf(fmaf(y.z, sc, sh), 0.f);
        h.w += fmaxf(fmaf(y.w, sc, sh), 0.f);
        hp[o] = h;
        ps += h.x + h.y + h.z + h.w;
    }
    if (do_pool) {
#pragma unroll
        for (int off = 16; off; off >>= 1) ps += __shfl_down_sync(0xffffffffu, ps, off);
        __shared__ float wsum[8];
        if ((threadIdx.x & 31) == 0) wsum[threadIdx.x >> 5] = ps;
        __syncthreads();
        if (threadIdx.x == 0) {
            float t = 0.f;
#pragma unroll
            for (int w = 0; w < 8; w++) t += wsum[w];
            atomicAdd(&g_pool[b * HH + f], t);
        }
    }
}

__global__ void head_kernel(const float* __restrict__ W1, const float* __restrict__ b1,
                            const float* __restrict__ W2, const float* __restrict__ b2,
                            float* __restrict__ out) {
    __shared__ float z[NB * HH];
    int tid = threadIdx.x;
    const float invN = 1.f / (float)NN;
    for (int idx = tid; idx < NB * HH; idx += 256) {
        int b = idx >> 6, j = idx & 63;
        float acc = b1[j];
#pragma unroll
        for (int k = 0; k < HH; k++)
            acc = fmaf(g_pool[b * HH + k] * invN, W1[k * HH + j], acc);
        z[idx] = fmaxf(acc, 0.f);
    }
    __syncthreads();
    for (int idx = tid; idx < NB * NDOUT; idx += 256) {
        int b = idx >> 7, o = idx & 127;
        float acc = b2[o];
#pragma unroll
        for (int j = 0; j < HH; j++)
            acc = fmaf(z[b * HH + j], W2[j * NDOUT + o], acc);
        out[idx] = acc;
    }
}

// ---------------- tf32 mma.sync GEMM ----------------------------------------
// D[f_out=64][node] = W^T @ A, A[k][node] is the natural feature-major layout.
// mode 0: A = [h ; agg], K=128.  mode 1: A = relu(bn(g_y)), K=64, in-place.
// CTA: 256 thr = 8 warps; tile = 128 nodes x 64 feats. warp: m16 x n64.
// Fused: bias, BN-stats (register accum -> quad shuffle -> global atomics).
#define STW 132   // padded smem stride (words) => conflict-free frag loads
__global__ __launch_bounds__(256) void mma_gemm(const float* __restrict__ W,
                                                const float* __restrict__ bias,
                                                int K, int mode, int useIn, int useOut,
                                                int tilesPerCta) {
    extern __shared__ char smem[];
    float* bias_s = (float*)smem;              // 256 B
    float* sc_s   = (float*)(smem + 256);
    float* sh_s   = (float*)(smem + 512);
    uint32_t* Ws  = (uint32_t*)(smem + 1024);              // 64 x STW
    uint32_t* As  = (uint32_t*)(smem + 1024 + 64*STW*4);   // K x STW

    const int tid = threadIdx.x, lid = tid & 31, wid = tid >> 5;
    const int m0 = (wid & 3) * 16;       // out-feature frag base
    const int nbase = (wid >> 2) * 64;   // node half
    const int r = lid >> 2, cq = lid & 3;

    if (tid < 64) bias_s[tid] = bias[tid];
    if (mode == 1 && tid >= 64 && tid < 128) {
        sc_s[tid - 64] = g_scale[useIn][tid - 64];
        sh_s[tid - 64] = g_shift[useIn][tid - 64];
    }
    for (int idx = tid; idx < K * 64; idx += 256) {        // Ws[m=f][k] = W[k][f]
        int k = idx >> 6, f = idx & 63;
        Ws[f * STW + k] = f2tf32(W[k * HH + f]);
    }

    float st0 = 0.f, q0 = 0.f, st1 = 0.f, q1 = 0.f;

    for (int t = 0; t < tilesPerCta; t++) {
        int T = blockIdx.x * tilesPerCta + t;
        int b = T >> 8;
        int n0 = (T & 255) << 7;

        __syncthreads();   // previous-iter readers done (also covers Ws fill at t=0)
        for (int idx = tid; idx < K * 32; idx += 256) {    // As[k][n], coalesced
            int k = idx >> 5, c4 = idx & 31;
            const float* src;
            if (mode == 0)
                src = ((k < HH) ? g_h : g_agg) + ((size_t)(b * HH + (k & 63))) * NN + n0 + c4 * 4;
            else
                src = g_y + ((size_t)(b * HH + k)) * NN + n0 + c4 * 4;
            float4 v = *(const float4*)src;
            if (mode == 1) {
                float sc = sc_s[k], sh = sh_s[k];
                v.x = fmaxf(fmaf(v.x, sc, sh), 0.f);
                v.y = fmaxf(fmaf(v.y, sc, sh), 0.f);
                v.z = fmaxf(fmaf(v.z, sc, sh), 0.f);
                v.w = fmaxf(fmaf(v.w, sc, sh), 0.f);
            }
            uint32_t* dst = &As[k * STW + c4 * 4];
            dst[0] = f2tf32(v.x); dst[1] = f2tf32(v.y);
            dst[2] = f2tf32(v.z); dst[3] = f2tf32(v.w);
        }
        __syncthreads();

        float acc[8][4];
        {
            float br = bias_s[m0 + r], br8 = bias_s[m0 + r + 8];
#pragma unroll
            for (int nt = 0; nt < 8; nt++) {
                acc[nt][0] = br; acc[nt][1] = br;
                acc[nt][2] = br8; acc[nt][3] = br8;
            }
        }

        for (int ks = 0; ks < K; ks += 8) {
            uint32_t a[4];
            const uint32_t* wr = &Ws[(m0 + r) * STW + ks + cq];
            a[0] = wr[0];
            a[1] = wr[8 * STW];
            a[2] = wr[4];
            a[3] = wr[8 * STW + 4];
            const uint32_t* brd = &As[(ks + cq) * STW + nbase + r];
#pragma unroll
            for (int nt = 0; nt < 8; nt++) {
                uint32_t bb[2];
                bb[0] = brd[nt * 8];
                bb[1] = brd[4 * STW + nt * 8];
                mma_tf32(acc[nt], a, bb);
            }
        }

        size_t base0 = ((size_t)(b * HH + m0 + r)) * NN + n0 + nbase;
        size_t base1 = base0 + (size_t)8 * NN;
#pragma unroll
        for (int nt = 0; nt < 8; nt++) {
            int nn = nt * 8 + 2 * cq;
            *(float2*)&g_y[base0 + nn] = make_float2(acc[nt][0], acc[nt][1]);
            *(float2*)&g_y[base1 + nn] = make_float2(acc[nt][2], acc[nt][3]);
            st0 += acc[nt][0] + acc[nt][1];
            q0  += acc[nt][0] * acc[nt][0] + acc[nt][1] * acc[nt][1];
            st1 += acc[nt][2] + acc[nt][3];
            q1  += acc[nt][2] * acc[nt][2] + acc[nt][3] * acc[nt][3];
        }
    }

#pragma unroll
    for (int d = 1; d < 4; d <<= 1) {
        st0 += __shfl_xor_sync(0xffffffffu, st0, d);
        q0  += __shfl_xor_sync(0xffffffffu, q0, d);
        st1 += __shfl_xor_sync(0xffffffffu, st1, d);
        q1  += __shfl_xor_sync(0xffffffffu, q1, d);
    }
    if (cq == 0) {
        atomicAdd(&g_stats[useOut][m0 + r], st0);
        atomicAdd(&g_stats[useOut][HH + m0 + r], q0);
        atomicAdd(&g_stats[useOut][m0 + r + 8], st1);
        atomicAdd(&g_stats[useOut][HH + m0 + r + 8], q1);
    }
}

// ---------------- driver ---------------------------------------------------
extern "C" void kernel_launch(void* const* d_in, const int* in_sizes, int n_in,
                              void* d_out, int out_size) {
    const float* x    = (const float*)d_in[0];
    const float* embW = (const float*)d_in[2];
    const float* embB = (const float*)d_in[3];
    const float* W1   = (const float*)d_in[4];
    const float* b1   = (const float*)d_in[5];
    const float* g1   = (const float*)d_in[6];
    const float* be1  = (const float*)d_in[7];
    const float* W2   = (const float*)d_in[8];
    const float* b2   = (const float*)d_in[9];
    const float* g2   = (const float*)d_in[10];
    const float* be2  = (const float*)d_in[11];
    const float* hW1  = (const float*)d_in[12];
    const float* hb1  = (const float*)d_in[13];
    const float* hW2  = (const float*)d_in[14];
    const float* hb2  = (const float*)d_in[15];
    float* out = (float*)d_out;

    const int SMEM_G1 = 1024 + 64 * STW * 4 + 128 * STW * 4;  // 102400
    const int SMEM_G2 = 1024 + 64 * STW * 4 + 64 * STW * 4;   //  68608
    cudaFuncSetAttribute(mma_gemm, cudaFuncAttributeMaxDynamicSharedMemorySize, SMEM_G1);

    const int TPC = 4;                      // 4 x 128-node tiles per CTA
    const int GRID = MROWS / 128 / TPC;     // 1024

    zero_kernel<<<1, 256>>>();
    embed_kernel<<<dim3(8, HH, NB), 256>>>(x, embW, embB);
    for (int l = 0; l < 3; l++) {
        agg_kernel<<<dim3(32, HH, NB), 256>>>();
        mma_gemm<<<GRID, 256, SMEM_G1>>>(W1 + l * 2 * HH * HH, b1 + l * HH,
                                         128, 0, 0, l * 2, TPC);
        norm_kernel<<<1, 64>>>(l * 2, g1 + l * HH, be1 + l * HH);
        mma_gemm<<<GRID, 256, SMEM_G2>>>(W2 + l * HH * HH, b2 + l * HH,
                                         64, 1, l * 2, l * 2 + 1, TPC);
        norm_kernel<<<1, 64>>>(l * 2 + 1, g2 + l * HH, be2 + l * HH);
        relu_res_kernel<<<dim3(4, HH, NB), 256>>>(l * 2 + 1, (l == 2) ? 1 : 0);
    }
    head_kernel<<<1, 256>>>(hW1, hb1, hW2, hb2, out);
}

// round 7
// speedup vs baseline: 1.8512x; 1.1448x over previous
#include <cuda_runtime.h>
#include <cstdint>

#define NB 16
#define NN 32768          // nodes = 128*256 torus
#define HH 64
#define NDOUT 128
#define MROWS (NB*NN)     // 524288
#define EPSBN 1e-5f
#define STW 136           // smem stride words: bank = 8*cq + r -> conflict-free b-frags

// ---------------- scratch (feature-major layout: [b][f][n]) ----------------
__device__ float g_h[NB*HH*NN];
__device__ float g_h2[NB*HH*NN];
__device__ float g_agg[NB*HH*NN];
__device__ float g_y[NB*HH*NN];
__device__ float g_stats[6][2*HH];
__device__ float g_pool[NB*HH];

// ---------------- helpers ---------------------------------------------------
__device__ __forceinline__ uint32_t f2tf32(float x) {
    uint32_t r;
    asm("cvt.rna.tf32.f32 %0, %1;" : "=r"(r) : "f"(x));
    return r;
}
__device__ __forceinline__ void mma_tf32(float* d, const uint32_t* a, const uint32_t* b) {
    asm volatile(
        "mma.sync.aligned.m16n8k8.row.col.f32.tf32.tf32.f32 "
        "{%0,%1,%2,%3}, {%4,%5,%6,%7}, {%8,%9}, {%0,%1,%2,%3};"
        : "+f"(d[0]), "+f"(d[1]), "+f"(d[2]), "+f"(d[3])
        : "r"(a[0]), "r"(a[1]), "r"(a[2]), "r"(a[3]), "r"(b[0]), "r"(b[1]));
}
__device__ __forceinline__ void bn_coef(int use, int f, const float* g, const float* be,
                                        float& sc, float& sh) {
    const float invM = 1.f / (float)MROWS;
    float s = g_stats[use][f], q = g_stats[use][HH + f];
    float m = s * invM;
    float v = q * invM - m * m;
    float r = rsqrtf(v + EPSBN);
    sc = g[f] * r;
    sh = fmaf(-m, sc, be[f]);
}

// ---------------- small kernels ---------------------------------------------
__global__ void zero_kernel() {
    int tid = threadIdx.x;
    float* s = &g_stats[0][0];
    for (int i = tid; i < 6 * 2 * HH; i += 256) s[i] = 0.f;
    for (int i = tid; i < NB * HH; i += 256) g_pool[i] = 0.f;
}

__global__ void embed_kernel(const float* __restrict__ x,
                             const float* __restrict__ W,
                             const float* __restrict__ bias) {
    int b = blockIdx.z, f = blockIdx.y;
    float w0 = W[f], w1 = W[HH + f], w2 = W[2 * HH + f], bb = bias[f];
    const float4* x0 = (const float4*)(x + (size_t)(b * 3 + 0) * NN);
    const float4* x1 = (const float4*)(x + (size_t)(b * 3 + 1) * NN);
    const float4* x2 = (const float4*)(x + (size_t)(b * 3 + 2) * NN);
    float4* hp = (float4*)(g_h + (size_t)(b * HH + f) * NN);
#pragma unroll
    for (int i = 0; i < 4; i++) {
        int idx = blockIdx.x * 1024 + threadIdx.x + i * 256;
        float4 a = x0[idx], c = x1[idx], d = x2[idx];
        float4 r;
        r.x = fmaxf(fmaf(a.x, w0, fmaf(c.x, w1, fmaf(d.x, w2, bb))), 0.f);
        r.y = fmaxf(fmaf(a.y, w0, fmaf(c.y, w1, fmaf(d.y, w2, bb))), 0.f);
        r.z = fmaxf(fmaf(a.z, w0, fmaf(c.z, w1, fmaf(d.z, w2, bb))), 0.f);
        r.w = fmaxf(fmaf(a.w, w0, fmaf(c.w, w1, fmaf(d.w, w2, bb))), 0.f);
        hp[idx] = r;
    }
}

// initial aggregate from g_h
__global__ void agg_kernel() {
    int b = blockIdx.z, f = blockIdx.y;
    const float* __restrict__ hp = g_h + (size_t)(b * HH + f) * NN;
    float* __restrict__ ap = g_agg + (size_t)(b * HH + f) * NN;
#pragma unroll
    for (int i = 0; i < 4; i++) {
        int n = blockIdx.x * 1024 + threadIdx.x + i * 256;
        int up = (n + 256) & 32767;
        int dn = (n + 32512) & 32767;
        int base = n & ~255, z = n & 255;
        int rt = base | ((z + 1) & 255);
        int lf = base | ((z - 1) & 255);
        ap[n] = 0.25f * (hp[up] + hp[dn] + hp[rt] + hp[lf]);
    }
}

// ---------------- fused: h_out = h_in + relu(bn(y)); agg = stencil(h_out) ---
// 8192-node chunk per block + 256-node halo each side staged in smem.
__global__ __launch_bounds__(256) void fused_res_agg(int hselIn,
                                                     const float* __restrict__ gamma,
                                                     const float* __restrict__ beta,
                                                     int use) {
    __shared__ float hb[8704];
    __shared__ float ss[2];
    int b = blockIdx.z, f = blockIdx.y, tid = threadIdx.x;
    if (tid == 0) {
        float sc, sh;
        bn_coef(use, f, gamma, beta, sc, sh);
        ss[0] = sc; ss[1] = sh;
    }
    __syncthreads();
    float sc = ss[0], sh = ss[1];
    const float* hin = hselIn ? g_h2 : g_h;
    float* hout = hselIn ? g_h : g_h2;
    size_t plane = (size_t)(b * HH + f) * NN;
    int n0 = blockIdx.x * 8192;

    for (int q4 = tid; q4 < 2176; q4 += 256) {
        int nh = (n0 - 256 + q4 * 4 + NN) & (NN - 1);
        float4 h = *(const float4*)(hin + plane + nh);
        float4 y = *(const float4*)(g_y + plane + nh);
        h.x += fmaxf(fmaf(y.x, sc, sh), 0.f);
        h.y += fmaxf(fmaf(y.y, sc, sh), 0.f);
        h.z += fmaxf(fmaf(y.z, sc, sh), 0.f);
        h.w += fmaxf(fmaf(y.w, sc, sh), 0.f);
        *(float4*)&hb[q4 * 4] = h;
        if (q4 >= 64 && q4 < 2112) *(float4*)(hout + plane + nh) = h;
    }
    __syncthreads();
    for (int q4 = tid; q4 < 2048; q4 += 256) {
        int i = 256 + q4 * 4;
        int n = n0 + q4 * 4;
        float4 a;
        float* ap = &a.x;
#pragma unroll
        for (int j = 0; j < 4; j++) {
            int zj = (n + j) & 255;
            int rowbase = i + j - zj;
            float lf = hb[rowbase + ((zj + 255) & 255)];
            float rt = hb[rowbase + ((zj + 1) & 255)];
            ap[j] = 0.25f * (hb[i + j - 256] + hb[i + j + 256] + lf + rt);
        }
        *(float4*)(g_agg + plane + n) = a;
    }
}

// ---------------- final layer: pool(h_in + relu(bn(y))), no h write ---------
__global__ __launch_bounds__(256) void relu_pool(int hselIn,
                                                 const float* __restrict__ gamma,
                                                 const float* __restrict__ beta,
                                                 int use) {
    __shared__ float ss[2];
    __shared__ float wsum[8];
    int b = blockIdx.z, f = blockIdx.y, tid = threadIdx.x;
    if (tid == 0) {
        float sc, sh;
        bn_coef(use, f, gamma, beta, sc, sh);
        ss[0] = sc; ss[1] = sh;
    }
    __syncthreads();
    float sc = ss[0], sh = ss[1];
    const float* hin = hselIn ? g_h2 : g_h;
    size_t plane = (size_t)(b * HH + f) * NN;
    int n0 = blockIdx.x * 8192;
    float ps = 0.f;
    for (int q4 = tid; q4 < 2048; q4 += 256) {
        int n = n0 + q4 * 4;
        float4 h = *(const float4*)(hin + plane + n);
        float4 y = *(const float4*)(g_y + plane + n);
        ps += h.x + fmaxf(fmaf(y.x, sc, sh), 0.f);
        ps += h.y + fmaxf(fmaf(y.y, sc, sh), 0.f);
        ps += h.z + fmaxf(fmaf(y.z, sc, sh), 0.f);
        ps += h.w + fmaxf(fmaf(y.w, sc, sh), 0.f);
    }
#pragma unroll
    for (int off = 16; off; off >>= 1) ps += __shfl_down_sync(0xffffffffu, ps, off);
    if ((tid & 31) == 0) wsum[tid >> 5] = ps;
    __syncthreads();
    if (tid == 0) {
        float t = 0.f;
#pragma unroll
        for (int w = 0; w < 8; w++) t += wsum[w];
        atomicAdd(&g_pool[b * HH + f], t);
    }
}

__global__ void head_kernel(const float* __restrict__ W1, const float* __restrict__ b1,
                            const float* __restrict__ W2, const float* __restrict__ b2,
                            float* __restrict__ out) {
    __shared__ float z[NB * HH];
    int tid = threadIdx.x;
    const float invN = 1.f / (float)NN;
    for (int idx = tid; idx < NB * HH; idx += 256) {
        int b = idx >> 6, j = idx & 63;
        float acc = b1[j];
#pragma unroll
        for (int k = 0; k < HH; k++)
            acc = fmaf(g_pool[b * HH + k] * invN, W1[k * HH + j], acc);
        z[idx] = fmaxf(acc, 0.f);
    }
    __syncthreads();
    for (int idx = tid; idx < NB * NDOUT; idx += 256) {
        int b = idx >> 7, o = idx & 127;
        float acc = b2[o];
#pragma unroll
        for (int j = 0; j < HH; j++)
            acc = fmaf(z[b * HH + j], W2[j * NDOUT + o], acc);
        out[idx] = acc;
    }
}

// ---------------- tf32 mma.sync GEMM ----------------------------------------
// D[f_out=64][node] = W^T @ A. Warp tile m32 x n32 (2 m-frags x 4 n-frags).
// Ws pre-packed in per-lane frag order (1 LDS.128 per a-frag); b-frags
// conflict-free via STW=136. BN folded into mode 1; bias+stats fused.
__global__ __launch_bounds__(256) void mma_gemm(const float* __restrict__ W,
                                                const float* __restrict__ bias,
                                                const float* __restrict__ gamma,
                                                const float* __restrict__ beta,
                                                int K, int ksb, int mode, int hsel,
                                                int useIn, int useOut, int tilesPerCta) {
    extern __shared__ char smem[];
    float* bias_s = (float*)smem;
    float* sc_s   = (float*)(smem + 256);
    float* sh_s   = (float*)(smem + 512);
    const int KS8 = K >> 3;
    uint4* Wp = (uint4*)(smem + 1024);                         // [4][KS8][32] frags
    uint32_t* As = (uint32_t*)(smem + 1024 + KS8 * 2048);      // K x STW

    const int tid = threadIdx.x, lid = tid & 31, wid = tid >> 5;
    const int r = lid >> 2, cq = lid & 3;
    const int mq = wid & 1, nq = wid >> 1;

    if (tid < 64) bias_s[tid] = bias[tid];
    if (mode == 1 && tid >= 64 && tid < 128) {
        float sc, sh;
        bn_coef(useIn, tid - 64, gamma, beta, sc, sh);
        sc_s[tid - 64] = sc; sh_s[tid - 64] = sh;
    }
    for (int e = tid; e < 4 * KS8 * 32; e += 256) {
        int lane = e & 31;
        int ks8 = (e >> 5) & (KS8 - 1);
        int fq = (e >> 5) >> ksb;
        int er = lane >> 2, ecq = lane & 3;
        int m0 = fq * 16, k = ks8 * 8 + ecq;
        uint4 w;
        w.x = f2tf32(W[k * HH + m0 + er]);
        w.y = f2tf32(W[k * HH + m0 + 8 + er]);
        w.z = f2tf32(W[(k + 4) * HH + m0 + er]);
        w.w = f2tf32(W[(k + 4) * HH + m0 + 8 + er]);
        Wp[e] = w;
    }

    const float* hbase = hsel ? g_h2 : g_h;
    float st[2][2] = {{0.f, 0.f}, {0.f, 0.f}};
    float sq[2][2] = {{0.f, 0.f}, {0.f, 0.f}};

    for (int t = 0; t < tilesPerCta; t++) {
        int T = blockIdx.x * tilesPerCta + t;
        int b = T >> 8;
        int n0 = (T & 255) << 7;

        __syncthreads();
        for (int idx = tid; idx < K * 32; idx += 256) {
            int k = idx >> 5, c4 = idx & 31;
            const float* src;
            if (mode == 0)
                src = ((k < HH) ? hbase : g_agg) + ((size_t)(b * HH + (k & 63))) * NN + n0 + c4 * 4;
            else
                src = g_y + ((size_t)(b * HH + k)) * NN + n0 + c4 * 4;
            float4 v = *(const float4*)src;
            if (mode == 1) {
                float sc = sc_s[k], sh = sh_s[k];
                v.x = fmaxf(fmaf(v.x, sc, sh), 0.f);
                v.y = fmaxf(fmaf(v.y, sc, sh), 0.f);
                v.z = fmaxf(fmaf(v.z, sc, sh), 0.f);
                v.w = fmaxf(fmaf(v.w, sc, sh), 0.f);
            }
            uint4 o;
            o.x = f2tf32(v.x); o.y = f2tf32(v.y);
            o.z = f2tf32(v.z); o.w = f2tf32(v.w);
            *(uint4*)&As[k * STW + c4 * 4] = o;
        }
        __syncthreads();

        float acc[2][4][4];
        {
            float b0 = bias_s[mq * 32 + r],      b1v = bias_s[mq * 32 + 8 + r];
            float b2v = bias_s[mq * 32 + 16 + r], b3 = bias_s[mq * 32 + 24 + r];
#pragma unroll
            for (int nt = 0; nt < 4; nt++) {
                acc[0][nt][0] = b0;  acc[0][nt][1] = b0;
                acc[0][nt][2] = b1v; acc[0][nt][3] = b1v;
                acc[1][nt][0] = b2v; acc[1][nt][1] = b2v;
                acc[1][nt][2] = b3;  acc[1][nt][3] = b3;
            }
        }

        for (int ks8 = 0; ks8 < KS8; ks8++) {
            uint4 A0 = Wp[(((mq * 2 + 0) << ksb) + ks8) * 32 + lid];
            uint4 A1 = Wp[(((mq * 2 + 1) << ksb) + ks8) * 32 + lid];
            const uint32_t* base = &As[(ks8 * 8 + cq) * STW + nq * 32 + r];
#pragma unroll
            for (int nt = 0; nt < 4; nt++) {
                uint32_t bb[2];
                bb[0] = base[nt * 8];
                bb[1] = base[4 * STW + nt * 8];
                mma_tf32(acc[0][nt], (const uint32_t*)&A0, bb);
                mma_tf32(acc[1][nt], (const uint32_t*)&A1, bb);
            }
        }

#pragma unroll
        for (int f = 0; f < 2; f++) {
            size_t base0 = ((size_t)(b * HH + mq * 32 + f * 16 + r)) * NN + n0 + nq * 32;
            size_t base1 = base0 + (size_t)8 * NN;
#pragma unroll
            for (int nt = 0; nt < 4; nt++) {
                int nn = nt * 8 + 2 * cq;
                *(float2*)&g_y[base0 + nn] = make_float2(acc[f][nt][0], acc[f][nt][1]);
                *(float2*)&g_y[base1 + nn] = make_float2(acc[f][nt][2], acc[f][nt][3]);
                st[f][0] += acc[f][nt][0] + acc[f][nt][1];
                sq[f][0] += acc[f][nt][0] * acc[f][nt][0] + acc[f][nt][1] * acc[f][nt][1];
                st[f][1] += acc[f][nt][2] + acc[f][nt][3];
                sq[f][1] += acc[f][nt][2] * acc[f][nt][2] + acc[f][nt][3] * acc[f][nt][3];
            }
        }
    }

#pragma unroll
    for (int d = 1; d < 4; d <<= 1) {
#pragma unroll
        for (int f = 0; f < 2; f++) {
#pragma unroll
            for (int hv = 0; hv < 2; hv++) {
                st[f][hv] += __shfl_xor_sync(0xffffffffu, st[f][hv], d);
                sq[f][hv] += __shfl_xor_sync(0xffffffffu, sq[f][hv], d);
            }
        }
    }
    if (cq == 0) {
#pragma unroll
        for (int f = 0; f < 2; f++) {
            int m = mq * 32 + f * 16 + r;
            atomicAdd(&g_stats[useOut][m], st[f][0]);
            atomicAdd(&g_stats[useOut][HH + m], sq[f][0]);
            atomicAdd(&g_stats[useOut][m + 8], st[f][1]);
            atomicAdd(&g_stats[useOut][HH + m + 8], sq[f][1]);
        }
    }
}

// ---------------- driver ---------------------------------------------------
extern "C" void kernel_launch(void* const* d_in, const int* in_sizes, int n_in,
                              void* d_out, int out_size) {
    const float* x    = (const float*)d_in[0];
    const float* embW = (const float*)d_in[2];
    const float* embB = (const float*)d_in[3];
    const float* W1   = (const float*)d_in[4];
    const float* b1   = (const float*)d_in[5];
    const float* g1   = (const float*)d_in[6];
    const float* be1  = (const float*)d_in[7];
    const float* W2   = (const float*)d_in[8];
    const float* b2   = (const float*)d_in[9];
    const float* g2   = (const float*)d_in[10];
    const float* be2  = (const float*)d_in[11];
    const float* hW1  = (const float*)d_in[12];
    const float* hb1  = (const float*)d_in[13];
    const float* hW2  = (const float*)d_in[14];
    const float* hb2  = (const float*)d_in[15];
    float* out = (float*)d_out;

    const int SMEM_G1 = 1024 + 16 * 2048 + 128 * STW * 4;  // 103424
    const int SMEM_G2 = 1024 + 8 * 2048 + 64 * STW * 4;    // 52224
    cudaFuncSetAttribute(mma_gemm, cudaFuncAttributeMaxDynamicSharedMemorySize, SMEM_G1);

    const int TPC = 4;
    const int GRID = MROWS / 128 / TPC;  // 1024

    zero_kernel<<<1, 256>>>();
    embed_kernel<<<dim3(8, HH, NB), 256>>>(x, embW, embB);
    agg_kernel<<<dim3(32, HH, NB), 256>>>();
    for (int l = 0; l < 3; l++) {
        int hsel = l & 1;  // l0: g_h, l1: g_h2, l2: g_h
        mma_gemm<<<GRID, 256, SMEM_G1>>>(W1 + l * 2 * HH * HH, b1 + l * HH,
                                         nullptr, nullptr,
                                         128, 4, 0, hsel, 0, l * 2, TPC);
        mma_gemm<<<GRID, 256, SMEM_G2>>>(W2 + l * HH * HH, b2 + l * HH,
                                         g1 + l * HH, be1 + l * HH,
                                         64, 3, 1, hsel, l * 2, l * 2 + 1, TPC);
        if (l < 2)
            fused_res_agg<<<dim3(4, HH, NB), 256>>>(hsel, g2 + l * HH, be2 + l * HH,
                                                    l * 2 + 1);
        else
            relu_pool<<<dim3(4, HH, NB), 256>>>(hsel, g2 + l * HH, be2 + l * HH,
                                                l * 2 + 1);
    }
    head_kernel<<<1, 256>>>(hW1, hb1, hW2, hb2, out);
}

// round 8
// speedup vs baseline: 2.1731x; 1.1738x over previous
#include <cuda_runtime.h>
#include <cstdint>

#define NB 16
#define NN 32768          // nodes = 128*256 torus
#define HH 64
#define NDOUT 128
#define MROWS (NB*NN)     // 524288
#define EPSBN 1e-5f
#define STW 136           // smem stride words: bank = 8*cq + r -> conflict-free b-frags
#define TPC 4

// ---------------- scratch (feature-major layout: [b][f][n]) ----------------
__device__ float g_h[NB*HH*NN];
__device__ float g_h2[NB*HH*NN];
__device__ float g_agg[NB*HH*NN];
__device__ float g_y[NB*HH*NN];
__device__ float g_stats[6][2*HH];
__device__ float g_pool[NB*HH];

// ---------------- helpers ---------------------------------------------------
__device__ __forceinline__ uint32_t f2tf32(float x) {
    uint32_t r;
    asm("cvt.rna.tf32.f32 %0, %1;" : "=r"(r) : "f"(x));
    return r;
}
__device__ __forceinline__ void mma_tf32(float* d, const uint32_t* a, const uint32_t* b) {
    asm volatile(
        "mma.sync.aligned.m16n8k8.row.col.f32.tf32.tf32.f32 "
        "{%0,%1,%2,%3}, {%4,%5,%6,%7}, {%8,%9}, {%0,%1,%2,%3};"
        : "+f"(d[0]), "+f"(d[1]), "+f"(d[2]), "+f"(d[3])
        : "r"(a[0]), "r"(a[1]), "r"(a[2]), "r"(a[3]), "r"(b[0]), "r"(b[1]));
}
__device__ __forceinline__ void bn_coef(int use, int f, const float* g, const float* be,
                                        float& sc, float& sh) {
    const float invM = 1.f / (float)MROWS;
    float s = g_stats[use][f], q = g_stats[use][HH + f];
    float m = s * invM;
    float v = q * invM - m * m;
    float r = rsqrtf(v + EPSBN);
    sc = g[f] * r;
    sh = fmaf(-m, sc, be[f]);
}
__device__ __forceinline__ void cpa16(uint32_t dst, const void* src) {
    asm volatile("cp.async.cg.shared.global [%0], [%1], 16;" :: "r"(dst), "l"(src));
}
__device__ __forceinline__ void cpcommit() {
    asm volatile("cp.async.commit_group;");
}
__device__ __forceinline__ void cpwait(int n) {
    switch (n) {
        case 0: asm volatile("cp.async.wait_group 0;"); break;
        case 1: asm volatile("cp.async.wait_group 1;"); break;
        case 2: asm volatile("cp.async.wait_group 2;"); break;
        default: asm volatile("cp.async.wait_group 3;"); break;
    }
}

// ---------------- small kernels ---------------------------------------------
__global__ void zero_kernel() {
    int tid = threadIdx.x;
    float* s = &g_stats[0][0];
    for (int i = tid; i < 6 * 2 * HH; i += 256) s[i] = 0.f;
    for (int i = tid; i < NB * HH; i += 256) g_pool[i] = 0.f;
}

__global__ void embed_kernel(const float* __restrict__ x,
                             const float* __restrict__ W,
                             const float* __restrict__ bias) {
    int b = blockIdx.z, f = blockIdx.y;
    float w0 = W[f], w1 = W[HH + f], w2 = W[2 * HH + f], bb = bias[f];
    const float4* x0 = (const float4*)(x + (size_t)(b * 3 + 0) * NN);
    const float4* x1 = (const float4*)(x + (size_t)(b * 3 + 1) * NN);
    const float4* x2 = (const float4*)(x + (size_t)(b * 3 + 2) * NN);
    float4* hp = (float4*)(g_h + (size_t)(b * HH + f) * NN);
#pragma unroll
    for (int i = 0; i < 4; i++) {
        int idx = blockIdx.x * 1024 + threadIdx.x + i * 256;
        float4 a = x0[idx], c = x1[idx], d = x2[idx];
        float4 r;
        r.x = fmaxf(fmaf(a.x, w0, fmaf(c.x, w1, fmaf(d.x, w2, bb))), 0.f);
        r.y = fmaxf(fmaf(a.y, w0, fmaf(c.y, w1, fmaf(d.y, w2, bb))), 0.f);
        r.z = fmaxf(fmaf(a.z, w0, fmaf(c.z, w1, fmaf(d.z, w2, bb))), 0.f);
        r.w = fmaxf(fmaf(a.w, w0, fmaf(c.w, w1, fmaf(d.w, w2, bb))), 0.f);
        hp[idx] = r;
    }
}

// initial aggregate from g_h
__global__ void agg_kernel() {
    int b = blockIdx.z, f = blockIdx.y;
    const float* __restrict__ hp = g_h + (size_t)(b * HH + f) * NN;
    float* __restrict__ ap = g_agg + (size_t)(b * HH + f) * NN;
#pragma unroll
    for (int i = 0; i < 4; i++) {
        int n = blockIdx.x * 1024 + threadIdx.x + i * 256;
        int up = (n + 256) & 32767;
        int dn = (n + 32512) & 32767;
        int base = n & ~255, z = n & 255;
        int rt = base | ((z + 1) & 255);
        int lf = base | ((z - 1) & 255);
        ap[n] = 0.25f * (hp[up] + hp[dn] + hp[rt] + hp[lf]);
    }
}

// ---------------- fused: h_out = h_in + relu(bn(y)); agg = stencil(h_out) ---
__global__ __launch_bounds__(256) void fused_res_agg(int hselIn,
                                                     const float* __restrict__ gamma,
                                                     const float* __restrict__ beta,
                                                     int use) {
    __shared__ float hb[8704];
    __shared__ float ss[2];
    int b = blockIdx.z, f = blockIdx.y, tid = threadIdx.x;
    if (tid == 0) {
        float sc, sh;
        bn_coef(use, f, gamma, beta, sc, sh);
        ss[0] = sc; ss[1] = sh;
    }
    __syncthreads();
    float sc = ss[0], sh = ss[1];
    const float* hin = hselIn ? g_h2 : g_h;
    float* hout = hselIn ? g_h : g_h2;
    size_t plane = (size_t)(b * HH + f) * NN;
    int n0 = blockIdx.x * 8192;

    for (int q4 = tid; q4 < 2176; q4 += 256) {
        int nh = (n0 - 256 + q4 * 4 + NN) & (NN - 1);
        float4 h = *(const float4*)(hin + plane + nh);
        float4 y = *(const float4*)(g_y + plane + nh);
        h.x += fmaxf(fmaf(y.x, sc, sh), 0.f);
        h.y += fmaxf(fmaf(y.y, sc, sh), 0.f);
        h.z += fmaxf(fmaf(y.z, sc, sh), 0.f);
        h.w += fmaxf(fmaf(y.w, sc, sh), 0.f);
        *(float4*)&hb[q4 * 4] = h;
        if (q4 >= 64 && q4 < 2112) *(float4*)(hout + plane + nh) = h;
    }
    __syncthreads();
    for (int q4 = tid; q4 < 2048; q4 += 256) {
        int i = 256 + q4 * 4;
        int n = n0 + q4 * 4;
        float4 a;
        float* ap = &a.x;
#pragma unroll
        for (int j = 0; j < 4; j++) {
            int zj = (n + j) & 255;
            int rowbase = i + j - zj;
            float lf = hb[rowbase + ((zj + 255) & 255)];
            float rt = hb[rowbase + ((zj + 1) & 255)];
            ap[j] = 0.25f * (hb[i + j - 256] + hb[i + j + 256] + lf + rt);
        }
        *(float4*)(g_agg + plane + n) = a;
    }
}

// ---------------- final layer: pool(h_in + relu(bn(y))), no h write ---------
__global__ __launch_bounds__(256) void relu_pool(int hselIn,
                                                 const float* __restrict__ gamma,
                                                 const float* __restrict__ beta,
                                                 int use) {
    __shared__ float ss[2];
    __shared__ float wsum[8];
    int b = blockIdx.z, f = blockIdx.y, tid = threadIdx.x;
    if (tid == 0) {
        float sc, sh;
        bn_coef(use, f, gamma, beta, sc, sh);
        ss[0] = sc; ss[1] = sh;
    }
    __syncthreads();
    float sc = ss[0], sh = ss[1];
    const float* hin = hselIn ? g_h2 : g_h;
    size_t plane = (size_t)(b * HH + f) * NN;
    int n0 = blockIdx.x * 8192;
    float ps = 0.f;
    for (int q4 = tid; q4 < 2048; q4 += 256) {
        int n = n0 + q4 * 4;
        float4 h = *(const float4*)(hin + plane + n);
        float4 y = *(const float4*)(g_y + plane + n);
        ps += h.x + fmaxf(fmaf(y.x, sc, sh), 0.f);
        ps += h.y + fmaxf(fmaf(y.y, sc, sh), 0.f);
        ps += h.z + fmaxf(fmaf(y.z, sc, sh), 0.f);
        ps += h.w + fmaxf(fmaf(y.w, sc, sh), 0.f);
    }
#pragma unroll
    for (int off = 16; off; off >>= 1) ps += __shfl_down_sync(0xffffffffu, ps, off);
    if ((tid & 31) == 0) wsum[tid >> 5] = ps;
    __syncthreads();
    if (tid == 0) {
        float t = 0.f;
#pragma unroll
        for (int w = 0; w < 8; w++) t += wsum[w];
        atomicAdd(&g_pool[b * HH + f], t);
    }
}

__global__ void head_kernel(const float* __restrict__ W1, const float* __restrict__ b1,
                            const float* __restrict__ W2, const float* __restrict__ b2,
                            float* __restrict__ out) {
    __shared__ float z[NB * HH];
    int tid = threadIdx.x;
    const float invN = 1.f / (float)NN;
    for (int idx = tid; idx < NB * HH; idx += 256) {
        int b = idx >> 6, j = idx & 63;
        float acc = b1[j];
#pragma unroll
        for (int k = 0; k < HH; k++)
            acc = fmaf(g_pool[b * HH + k] * invN, W1[k * HH + j], acc);
        z[idx] = fmaxf(acc, 0.f);
    }
    __syncthreads();
    for (int idx = tid; idx < NB * NDOUT; idx += 256) {
        int b = idx >> 7, o = idx & 127;
        float acc = b2[o];
#pragma unroll
        for (int j = 0; j < HH; j++)
            acc = fmaf(z[b * HH + j], W2[j * NDOUT + o], acc);
        out[idx] = acc;
    }
}

// ---------------- GEMM1: y = W1^T @ [h ; agg], K=128, cp.async pipelined ----
__global__ __launch_bounds__(256) void mma_gemm1(const float* __restrict__ W,
                                                 const float* __restrict__ bias,
                                                 int hsel, int useOut) {
    extern __shared__ char smem[];
    float* bias_s = (float*)smem;
    uint4* Wp = (uint4*)(smem + 1024);                    // [4][16][32] frags
    uint32_t* As = (uint32_t*)(smem + 1024 + 32768);      // 128 x STW
    const uint32_t As_u = (uint32_t)__cvta_generic_to_shared(As);

    const int tid = threadIdx.x, lid = tid & 31, wid = tid >> 5;
    const int r = lid >> 2, cq = lid & 3;
    const int mq = wid & 1, nq = wid >> 1;
    const float* hbase = hsel ? g_h2 : g_h;

    if (tid < 64) bias_s[tid] = bias[tid];
    for (int e = tid; e < 2048; e += 256) {
        int lane = e & 31;
        int ks8 = (e >> 5) & 15;
        int fq = e >> 9;
        int er = lane >> 2, ecq = lane & 3;
        int m0 = fq * 16, k = ks8 * 8 + ecq;
        uint4 w;
        w.x = f2tf32(W[k * HH + m0 + er]);
        w.y = f2tf32(W[k * HH + m0 + 8 + er]);
        w.z = f2tf32(W[(k + 4) * HH + m0 + er]);
        w.w = f2tf32(W[(k + 4) * HH + m0 + 8 + er]);
        Wp[e] = w;
    }

    float st[2][2] = {{0.f, 0.f}, {0.f, 0.f}};
    float sq[2][2] = {{0.f, 0.f}, {0.f, 0.f}};

    // prologue: issue all 4 chunks of tile 0
    {
        int T = blockIdx.x * TPC;
        int b = T >> 8, n0 = (T & 255) << 7;
        for (int c = 0; c < 4; c++) {
#pragma unroll
            for (int i = 0; i < 4; i++) {
                int idx = tid + i * 256;
                int k = c * 32 + (idx >> 5), c4 = idx & 31;
                const float* src = ((k < HH) ? hbase : g_agg) +
                                   ((size_t)(b * HH + (k & 63))) * NN + n0 + c4 * 4;
                cpa16(As_u + (uint32_t)(k * STW + c4 * 4) * 4, src);
            }
            cpcommit();
        }
    }

    for (int t = 0; t < TPC; t++) {
        int T = blockIdx.x * TPC + t;
        int b = T >> 8, n0 = (T & 255) << 7;

        float acc[2][4][4];
        {
            float b0 = bias_s[mq * 32 + r],       b1v = bias_s[mq * 32 + 8 + r];
            float b2v = bias_s[mq * 32 + 16 + r], b3 = bias_s[mq * 32 + 24 + r];
#pragma unroll
            for (int nt = 0; nt < 4; nt++) {
                acc[0][nt][0] = b0;  acc[0][nt][1] = b0;
                acc[0][nt][2] = b1v; acc[0][nt][3] = b1v;
                acc[1][nt][0] = b2v; acc[1][nt][1] = b2v;
                acc[1][nt][2] = b3;  acc[1][nt][3] = b3;
            }
        }

        for (int c = 0; c < 4; c++) {
            cpwait(3 - c);
            __syncthreads();
#pragma unroll
            for (int j = 0; j < 4; j++) {
                int ks8 = c * 4 + j;
                uint4 A0 = Wp[((mq * 2 + 0) * 16 + ks8) * 32 + lid];
                uint4 A1 = Wp[((mq * 2 + 1) * 16 + ks8) * 32 + lid];
                const uint32_t* base = &As[(ks8 * 8 + cq) * STW + nq * 32 + r];
#pragma unroll
                for (int nt = 0; nt < 4; nt++) {
                    uint32_t bb[2];
                    bb[0] = base[nt * 8];
                    bb[1] = base[4 * STW + nt * 8];
                    mma_tf32(acc[0][nt], (const uint32_t*)&A0, bb);
                    mma_tf32(acc[1][nt], (const uint32_t*)&A1, bb);
                }
            }
        }
        __syncthreads();   // all warps done reading As

        if (t + 1 < TPC) {   // overlap next tile's copies with epilogue
            int T2 = T + 1;
            int b2 = T2 >> 8, n02 = (T2 & 255) << 7;
            for (int c = 0; c < 4; c++) {
#pragma unroll
                for (int i = 0; i < 4; i++) {
                    int idx = tid + i * 256;
                    int k = c * 32 + (idx >> 5), c4 = idx & 31;
                    const float* src = ((k < HH) ? hbase : g_agg) +
                                       ((size_t)(b2 * HH + (k & 63))) * NN + n02 + c4 * 4;
                    cpa16(As_u + (uint32_t)(k * STW + c4 * 4) * 4, src);
                }
                cpcommit();
            }
        }

#pragma unroll
        for (int f = 0; f < 2; f++) {
            size_t base0 = ((size_t)(b * HH + mq * 32 + f * 16 + r)) * NN + n0 + nq * 32;
            size_t base1 = base0 + (size_t)8 * NN;
#pragma unroll
            for (int nt = 0; nt < 4; nt++) {
                int nn = nt * 8 + 2 * cq;
                *(float2*)&g_y[base0 + nn] = make_float2(acc[f][nt][0], acc[f][nt][1]);
                *(float2*)&g_y[base1 + nn] = make_float2(acc[f][nt][2], acc[f][nt][3]);
                st[f][0] += acc[f][nt][0] + acc[f][nt][1];
                sq[f][0] += acc[f][nt][0] * acc[f][nt][0] + acc[f][nt][1] * acc[f][nt][1];
                st[f][1] += acc[f][nt][2] + acc[f][nt][3];
                sq[f][1] += acc[f][nt][2] * acc[f][nt][2] + acc[f][nt][3] * acc[f][nt][3];
            }
        }
    }

#pragma unroll
    for (int d = 1; d < 4; d <<= 1)
#pragma unroll
        for (int f = 0; f < 2; f++)
#pragma unroll
            for (int hv = 0; hv < 2; hv++) {
                st[f][hv] += __shfl_xor_sync(0xffffffffu, st[f][hv], d);
                sq[f][hv] += __shfl_xor_sync(0xffffffffu, sq[f][hv], d);
            }
    if (cq == 0)
#pragma unroll
        for (int f = 0; f < 2; f++) {
            int m = mq * 32 + f * 16 + r;
            atomicAdd(&g_stats[useOut][m], st[f][0]);
            atomicAdd(&g_stats[useOut][HH + m], sq[f][0]);
            atomicAdd(&g_stats[useOut][m + 8], st[f][1]);
            atomicAdd(&g_stats[useOut][HH + m + 8], sq[f][1]);
        }
}

// ---------------- GEMM2: y = W2^T @ relu(bn(y)), K=64, reg-pipelined --------
__global__ __launch_bounds__(256) void mma_gemm2(const float* __restrict__ W,
                                                 const float* __restrict__ bias,
                                                 const float* __restrict__ gamma,
                                                 const float* __restrict__ beta,
                                                 int useIn, int useOut) {
    extern __shared__ char smem[];
    float* bias_s = (float*)smem;
    float* sc_s   = (float*)(smem + 256);
    float* sh_s   = (float*)(smem + 512);
    uint4* Wp = (uint4*)(smem + 1024);                    // [4][8][32]
    uint32_t* As = (uint32_t*)(smem + 1024 + 16384);      // 64 x STW

    const int tid = threadIdx.x, lid = tid & 31, wid = tid >> 5;
    const int r = lid >> 2, cq = lid & 3;
    const int mq = wid & 1, nq = wid >> 1;

    if (tid < 64) bias_s[tid] = bias[tid];
    if (tid >= 64 && tid < 128) {
        float sc, sh;
        bn_coef(useIn, tid - 64, gamma, beta, sc, sh);
        sc_s[tid - 64] = sc; sh_s[tid - 64] = sh;
    }
    for (int e = tid; e < 1024; e += 256) {
        int lane = e & 31;
        int ks8 = (e >> 5) & 7;
        int fq = e >> 8;
        int er = lane >> 2, ecq = lane & 3;
        int m0 = fq * 16, k = ks8 * 8 + ecq;
        uint4 w;
        w.x = f2tf32(W[k * HH + m0 + er]);
        w.y = f2tf32(W[k * HH + m0 + 8 + er]);
        w.z = f2tf32(W[(k + 4) * HH + m0 + er]);
        w.w = f2tf32(W[(k + 4) * HH + m0 + 8 + er]);
        Wp[e] = w;
    }
    __syncthreads();   // sc_s/sh_s ready before first STS transform

    const int myk = tid >> 5;        // task decode for fills: idx = tid + i*256
    const int myc4 = tid & 31;       // (k advances by 8 per i)

    float st[2][2] = {{0.f, 0.f}, {0.f, 0.f}};
    float sq[2][2] = {{0.f, 0.f}, {0.f, 0.f}};

    float4 pfA[4], pfB[4];
    auto loadc = [&](int t, int c, float4* pf) {
        int T = blockIdx.x * TPC + t;
        int b = T >> 8, n0 = (T & 255) << 7;
#pragma unroll
        for (int i = 0; i < 4; i++) {
            int k = c * 32 + myk + i * 8;
            pf[i] = *(const float4*)(g_y + ((size_t)(b * HH + k)) * NN + n0 + myc4 * 4);
        }
    };
    auto stsc = [&](int c, const float4* pf) {
#pragma unroll
        for (int i = 0; i < 4; i++) {
            int k = c * 32 + myk + i * 8;
            float sc = sc_s[k], sh = sh_s[k];
            float4 v = pf[i];
            uint4 o;
            o.x = __float_as_uint(fmaxf(fmaf(v.x, sc, sh), 0.f));
            o.y = __float_as_uint(fmaxf(fmaf(v.y, sc, sh), 0.f));
            o.z = __float_as_uint(fmaxf(fmaf(v.z, sc, sh), 0.f));
            o.w = __float_as_uint(fmaxf(fmaf(v.w, sc, sh), 0.f));
            *(uint4*)&As[k * STW + myc4 * 4] = o;
        }
    };
    auto mmachunk = [&](int c, float acc[2][4][4]) {
#pragma unroll
        for (int j = 0; j < 4; j++) {
            int ks8 = c * 4 + j;
            uint4 A0 = Wp[((mq * 2 + 0) * 8 + ks8) * 32 + lid];
            uint4 A1 = Wp[((mq * 2 + 1) * 8 + ks8) * 32 + lid];
            const uint32_t* base = &As[(ks8 * 8 + cq) * STW + nq * 32 + r];
#pragma unroll
            for (int nt = 0; nt < 4; nt++) {
                uint32_t bb[2];
                bb[0] = base[nt * 8];
                bb[1] = base[4 * STW + nt * 8];
                mma_tf32(acc[0][nt], (const uint32_t*)&A0, bb);
                mma_tf32(acc[1][nt], (const uint32_t*)&A1, bb);
            }
        }
    };

    loadc(0, 0, pfA);
    for (int t = 0; t < TPC; t++) {
        int T = blockIdx.x * TPC + t;
        int b = T >> 8, n0 = (T & 255) << 7;

        stsc(0, pfA);
        loadc(t, 1, pfB);
        __syncthreads();            // chunk 0 visible

        float acc[2][4][4];
        {
            float b0 = bias_s[mq * 32 + r],       b1v = bias_s[mq * 32 + 8 + r];
            float b2v = bias_s[mq * 32 + 16 + r], b3 = bias_s[mq * 32 + 24 + r];
#pragma unroll
            for (int nt = 0; nt < 4; nt++) {
                acc[0][nt][0] = b0;  acc[0][nt][1] = b0;
                acc[0][nt][2] = b1v; acc[0][nt][3] = b1v;
                acc[1][nt][0] = b2v; acc[1][nt][1] = b2v;
                acc[1][nt][2] = b3;  acc[1][nt][3] = b3;
            }
        }

        mmachunk(0, acc);
        stsc(1, pfB);               // disjoint region: safe during chunk-0 MMAs
        if (t + 1 < TPC) loadc(t + 1, 0, pfA);
        __syncthreads();            // chunk 1 visible + all chunk-0 reads done
        mmachunk(1, acc);

#pragma unroll
        for (int f = 0; f < 2; f++) {
            size_t base0 = ((size_t)(b * HH + mq * 32 + f * 16 + r)) * NN + n0 + nq * 32;
            size_t base1 = base0 + (size_t)8 * NN;
#pragma unroll
            for (int nt = 0; nt < 4; nt++) {
                int nn = nt * 8 + 2 * cq;
                *(float2*)&g_y[base0 + nn] = make_float2(acc[f][nt][0], acc[f][nt][1]);
                *(float2*)&g_y[base1 + nn] = make_float2(acc[f][nt][2], acc[f][nt][3]);
                st[f][0] += acc[f][nt][0] + acc[f][nt][1];
                sq[f][0] += acc[f][nt][0] * acc[f][nt][0] + acc[f][nt][1] * acc[f][nt][1];
                st[f][1] += acc[f][nt][2] + acc[f][nt][3];
                sq[f][1] += acc[f][nt][2] * acc[f][nt][2] + acc[f][nt][3] * acc[f][nt][3];
            }
        }
        __syncthreads();            // all reads of As done before next tile's STS
    }

#pragma unroll
    for (int d = 1; d < 4; d <<= 1)
#pragma unroll
        for (int f = 0; f < 2; f++)
#pragma unroll
            for (int hv = 0; hv < 2; hv++) {
                st[f][hv] += __shfl_xor_sync(0xffffffffu, st[f][hv], d);
                sq[f][hv] += __shfl_xor_sync(0xffffffffu, sq[f][hv], d);
            }
    if (cq == 0)
#pragma unroll
        for (int f = 0; f < 2; f++) {
            int m = mq * 32 + f * 16 + r;
            atomicAdd(&g_stats[useOut][m], st[f][0]);
            atomicAdd(&g_stats[useOut][HH + m], sq[f][0]);
            atomicAdd(&g_stats[useOut][m + 8], st[f][1]);
            atomicAdd(&g_stats[useOut][HH + m + 8], sq[f][1]);
        }
}

// ---------------- driver ---------------------------------------------------
extern "C" void kernel_launch(void* const* d_in, const int* in_sizes, int n_in,
                              void* d_out, int out_size) {
    const float* x    = (const float*)d_in[0];
    const float* embW = (const float*)d_in[2];
    const float* embB = (const float*)d_in[3];
    const float* W1   = (const float*)d_in[4];
    const float* b1   = (const float*)d_in[5];
    const float* g1   = (const float*)d_in[6];
    const float* be1  = (const float*)d_in[7];
    const float* W2   = (const float*)d_in[8];
    const float* b2   = (const float*)d_in[9];
    const float* g2   = (const float*)d_in[10];
    const float* be2  = (const float*)d_in[11];
    const float* hW1  = (const float*)d_in[12];
    const float* hb1  = (const float*)d_in[13];
    const float* hW2  = (const float*)d_in[14];
    const float* hb2  = (const float*)d_in[15];
    float* out = (float*)d_out;

    const int SMEM_G1 = 1024 + 32768 + 128 * STW * 4;  // 103424
    const int SMEM_G2 = 1024 + 16384 + 64 * STW * 4;   //  52224
    cudaFuncSetAttribute(mma_gemm1, cudaFuncAttributeMaxDynamicSharedMemorySize, SMEM_G1);
    cudaFuncSetAttribute(mma_gemm2, cudaFuncAttributeMaxDynamicSharedMemorySize, SMEM_G2);

    const int GRID = MROWS / 128 / TPC;  // 1024

    zero_kernel<<<1, 256>>>();
    embed_kernel<<<dim3(8, HH, NB), 256>>>(x, embW, embB);
    agg_kernel<<<dim3(32, HH, NB), 256>>>();
    for (int l = 0; l < 3; l++) {
        int hsel = l & 1;  // l0: g_h, l1: g_h2, l2: g_h
        mma_gemm1<<<GRID, 256, SMEM_G1>>>(W1 + l * 2 * HH * HH, b1 + l * HH, hsel, l * 2);
        mma_gemm2<<<GRID, 256, SMEM_G2>>>(W2 + l * HH * HH, b2 + l * HH,
                                          g1 + l * HH, be1 + l * HH, l * 2, l * 2 + 1);
        if (l < 2)
            fused_res_agg<<<dim3(4, HH, NB), 256>>>(hsel, g2 + l * HH, be2 + l * HH,
                                                    l * 2 + 1);
        else
            relu_pool<<<dim3(4, HH, NB), 256>>>(hsel, g2 + l * HH, be2 + l * HH,
                                                l * 2 + 1);
    }
    head_kernel<<<1, 256>>>(hW1, hb1, hW2, hb2, out);
}

// round 11
// speedup vs baseline: 2.8349x; 1.3046x over previous
#include <cuda_runtime.h>
#include <cuda_fp16.h>
#include <cstdint>

#define NB 16
#define NN 32768          // nodes = 128*256 torus
#define HH 64
#define NDOUT 128
#define MROWS (NB*NN)     // 524288
#define EPSBN 1e-5f
#define RB 272            // As row bytes: 256 data + 16 pad -> conflict-free ldmatrix
#define TPC 4

// ---------------- scratch (feature-major layout: [b][f][n]) ----------------
__device__ __half g_h[NB*HH*NN];     // trunk ping
__device__ __half g_h2[NB*HH*NN];    // trunk pong
__device__ __half g_agg[NB*HH*NN];   // stencil aggregate (gemm1 input)
__device__ float  g_y[NB*HH*NN];     // gemm outputs (pre-BN) -- fp32 for BN precision
__device__ float  g_stats[6][2*HH];
__device__ float  g_pool[NB*HH];

// ---------------- helpers ---------------------------------------------------
__device__ __forceinline__ float2 h2f(uint32_t u) {
    __half2 h = *(__half2*)&u;
    return __half22float2(h);
}
__device__ __forceinline__ uint32_t f2h(float a, float b) {
    __half2 h = __floats2half2_rn(a, b);
    return *(uint32_t*)&h;
}
__device__ __forceinline__ void u4tof8(uint4 u, float* f) {
    float2 a = h2f(u.x), b = h2f(u.y), c = h2f(u.z), d = h2f(u.w);
    f[0] = a.x; f[1] = a.y; f[2] = b.x; f[3] = b.y;
    f[4] = c.x; f[5] = c.y; f[6] = d.x; f[7] = d.y;
}
__device__ __forceinline__ uint4 f8tou4(const float* f) {
    uint4 u;
    u.x = f2h(f[0], f[1]); u.y = f2h(f[2], f[3]);
    u.z = f2h(f[4], f[5]); u.w = f2h(f[6], f[7]);
    return u;
}
__device__ __forceinline__ void mma_f16(float* d, const uint4& a, uint32_t b0, uint32_t b1) {
    asm volatile(
        "mma.sync.aligned.m16n8k16.row.col.f32.f16.f16.f32 "
        "{%0,%1,%2,%3}, {%4,%5,%6,%7}, {%8,%9}, {%0,%1,%2,%3};"
        : "+f"(d[0]), "+f"(d[1]), "+f"(d[2]), "+f"(d[3])
        : "r"(a.x), "r"(a.y), "r"(a.z), "r"(a.w), "r"(b0), "r"(b1));
}
#define LDMX4T(r0, r1, r2, r3, addr) \
    asm volatile("ldmatrix.sync.aligned.m8n8.x4.trans.shared.b16 {%0,%1,%2,%3}, [%4];" \
        : "=r"(r0), "=r"(r1), "=r"(r2), "=r"(r3) : "r"(addr))
__device__ __forceinline__ void bn_coef(int use, int f, const float* g, const float* be,
                                        float& sc, float& sh) {
    const float invM = 1.f / (float)MROWS;
    float s = g_stats[use][f], q = g_stats[use][HH + f];
    float m = s * invM;
    float v = q * invM - m * m;
    float r = rsqrtf(v + EPSBN);
    sc = g[f] * r;
    sh = fmaf(-m, sc, be[f]);
}
__device__ __forceinline__ void cpa16(uint32_t dst, const void* src) {
    asm volatile("cp.async.cg.shared.global [%0], [%1], 16;" :: "r"(dst), "l"(src));
}
__device__ __forceinline__ void cpcommit() { asm volatile("cp.async.commit_group;"); }
__device__ __forceinline__ void cpwait(int n) {
    switch (n) {
        case 0: asm volatile("cp.async.wait_group 0;"); break;
        case 1: asm volatile("cp.async.wait_group 1;"); break;
        case 2: asm volatile("cp.async.wait_group 2;"); break;
        default: asm volatile("cp.async.wait_group 3;"); break;
    }
}

// ---------------- small kernels ---------------------------------------------
__global__ void zero_kernel() {
    int tid = threadIdx.x;
    float* s = &g_stats[0][0];
    for (int i = tid; i < 6 * 2 * HH; i += 256) s[i] = 0.f;
    for (int i = tid; i < NB * HH; i += 256) g_pool[i] = 0.f;
}

// h[b][f][n] = relu(sum_c x[b][c][n] W[c][f] + b[f]) -> fp16
__global__ void embed_kernel(const float* __restrict__ x,
                             const float* __restrict__ W,
                             const float* __restrict__ bias) {
    int b = blockIdx.z, f = blockIdx.y;
    float w0 = W[f], w1 = W[HH + f], w2 = W[2 * HH + f], bb = bias[f];
    int n = blockIdx.x * 2048 + threadIdx.x * 8;
    const float* xb = x + (size_t)(b * 3) * NN + n;
    float r[8];
#pragma unroll
    for (int h = 0; h < 2; h++) {
        float4 a = *(const float4*)(xb + h * 4);
        float4 c = *(const float4*)(xb + NN + h * 4);
        float4 d = *(const float4*)(xb + 2 * NN + h * 4);
        r[h*4+0] = fmaxf(fmaf(a.x, w0, fmaf(c.x, w1, fmaf(d.x, w2, bb))), 0.f);
        r[h*4+1] = fmaxf(fmaf(a.y, w0, fmaf(c.y, w1, fmaf(d.y, w2, bb))), 0.f);
        r[h*4+2] = fmaxf(fmaf(a.z, w0, fmaf(c.z, w1, fmaf(d.z, w2, bb))), 0.f);
        r[h*4+3] = fmaxf(fmaf(a.w, w0, fmaf(c.w, w1, fmaf(d.w, w2, bb))), 0.f);
    }
    *(uint4*)(g_h + (size_t)(b * HH + f) * NN + n) = f8tou4(r);
}

// initial aggregate from g_h (layer 0)
__global__ void agg_kernel() {
    int b = blockIdx.z, f = blockIdx.y;
    const __half* hp = g_h + (size_t)(b * HH + f) * NN;
    int n = blockIdx.x * 2048 + threadIdx.x * 8;
    uint4 u8 = *(const uint4*)(hp + ((n + 256) & 32767));
    uint4 d8 = *(const uint4*)(hp + ((n - 256) & 32767));
    uint4 c8 = *(const uint4*)(hp + n);
    float lf = __half2float(hp[((n & 255) == 0) ? n + 255 : n - 1]);
    float rt = __half2float(hp[(((n + 7) & 255) == 255) ? n - 248 : n + 8]);
    float u[8], d[8], c[8], o[8];
    u4tof8(u8, u); u4tof8(d8, d); u4tof8(c8, c);
#pragma unroll
    for (int j = 0; j < 8; j++) {
        float L = (j == 0) ? lf : c[j - 1];
        float R = (j == 7) ? rt : c[j + 1];
        o[j] = 0.25f * (u[j] + d[j] + L + R);
    }
    *(uint4*)(g_agg + (size_t)(b * HH + f) * NN + n) = f8tou4(o);
}

// ---------------- fused: h_out = h_in + relu(bn(y)); agg = stencil(h_out) ---
__global__ __launch_bounds__(256) void fused_res_agg(int hselIn,
                                                     const float* __restrict__ gamma,
                                                     const float* __restrict__ beta,
                                                     int use) {
    __shared__ float hb[8704];
    __shared__ float ss[2];
    int b = blockIdx.z, f = blockIdx.y, tid = threadIdx.x;
    if (tid == 0) {
        float sc, sh;
        bn_coef(use, f, gamma, beta, sc, sh);
        ss[0] = sc; ss[1] = sh;
    }
    __syncthreads();
    float sc = ss[0], sh = ss[1];
    const __half* hin = hselIn ? g_h2 : g_h;
    __half* hout = hselIn ? g_h : g_h2;
    size_t plane = (size_t)(b * HH + f) * NN;
    int n0 = blockIdx.x * 8192;

    for (int q8 = tid; q8 < 1088; q8 += 256) {
        int nh = (n0 - 256 + q8 * 8) & 32767;
        float hf[8];
        u4tof8(*(const uint4*)(hin + plane + nh), hf);
        float4 y0 = *(const float4*)(g_y + plane + nh);
        float4 y1 = *(const float4*)(g_y + plane + nh + 4);
        hf[0] += fmaxf(fmaf(y0.x, sc, sh), 0.f);
        hf[1] += fmaxf(fmaf(y0.y, sc, sh), 0.f);
        hf[2] += fmaxf(fmaf(y0.z, sc, sh), 0.f);
        hf[3] += fmaxf(fmaf(y0.w, sc, sh), 0.f);
        hf[4] += fmaxf(fmaf(y1.x, sc, sh), 0.f);
        hf[5] += fmaxf(fmaf(y1.y, sc, sh), 0.f);
        hf[6] += fmaxf(fmaf(y1.z, sc, sh), 0.f);
        hf[7] += fmaxf(fmaf(y1.w, sc, sh), 0.f);
        *(float4*)&hb[q8 * 8] = make_float4(hf[0], hf[1], hf[2], hf[3]);
        *(float4*)&hb[q8 * 8 + 4] = make_float4(hf[4], hf[5], hf[6], hf[7]);
        if (q8 >= 32 && q8 < 1056) *(uint4*)(hout + plane + nh) = f8tou4(hf);
    }
    __syncthreads();
    for (int q8 = tid; q8 < 1024; q8 += 256) {
        int i = 256 + q8 * 8;
        int n = n0 + q8 * 8;
        float o[8];
#pragma unroll
        for (int j = 0; j < 8; j++) {
            int zj = (n + j) & 255;
            int rowbase = i + j - zj;
            float lf = hb[rowbase + ((zj + 255) & 255)];
            float rt = hb[rowbase + ((zj + 1) & 255)];
            o[j] = 0.25f * (hb[i + j - 256] + hb[i + j + 256] + lf + rt);
        }
        *(uint4*)(g_agg + plane + n) = f8tou4(o);
    }
}

// ---------------- final layer: pool(h_in + relu(bn(y))), no h write ---------
__global__ __launch_bounds__(256) void relu_pool(int hselIn,
                                                 const float* __restrict__ gamma,
                                                 const float* __restrict__ beta,
                                                 int use) {
    __shared__ float ss[2];
    __shared__ float wsum[8];
    int b = blockIdx.z, f = blockIdx.y, tid = threadIdx.x;
    if (tid == 0) {
        float sc, sh;
        bn_coef(use, f, gamma, beta, sc, sh);
        ss[0] = sc; ss[1] = sh;
    }
    __syncthreads();
    float sc = ss[0], sh = ss[1];
    const __half* hin = hselIn ? g_h2 : g_h;
    size_t plane = (size_t)(b * HH + f) * NN;
    int n0 = blockIdx.x * 8192;
    float ps = 0.f;
    for (int q8 = tid; q8 < 1024; q8 += 256) {
        int n = n0 + q8 * 8;
        float hf[8];
        u4tof8(*(const uint4*)(hin + plane + n), hf);
        float4 y0 = *(const float4*)(g_y + plane + n);
        float4 y1 = *(const float4*)(g_y + plane + n + 4);
        ps += hf[0] + fmaxf(fmaf(y0.x, sc, sh), 0.f);
        ps += hf[1] + fmaxf(fmaf(y0.y, sc, sh), 0.f);
        ps += hf[2] + fmaxf(fmaf(y0.z, sc, sh), 0.f);
        ps += hf[3] + fmaxf(fmaf(y0.w, sc, sh), 0.f);
        ps += hf[4] + fmaxf(fmaf(y1.x, sc, sh), 0.f);
        ps += hf[5] + fmaxf(fmaf(y1.y, sc, sh), 0.f);
        ps += hf[6] + fmaxf(fmaf(y1.z, sc, sh), 0.f);
        ps += hf[7] + fmaxf(fmaf(y1.w, sc, sh), 0.f);
    }
#pragma unroll
    for (int off = 16; off; off >>= 1) ps += __shfl_down_sync(0xffffffffu, ps, off);
    if ((tid & 31) == 0) wsum[tid >> 5] = ps;
    __syncthreads();
    if (tid == 0) {
        float t = 0.f;
#pragma unroll
        for (int w = 0; w < 8; w++) t += wsum[w];
        atomicAdd(&g_pool[b * HH + f], t);
    }
}

__global__ void head_kernel(const float* __restrict__ W1, const float* __restrict__ b1,
                            const float* __restrict__ W2, const float* __restrict__ b2,
                            float* __restrict__ out) {
    __shared__ float z[NB * HH];
    int tid = threadIdx.x;
    const float invN = 1.f / (float)NN;
    for (int idx = tid; idx < NB * HH; idx += 256) {
        int b = idx >> 6, j = idx & 63;
        float acc = b1[j];
#pragma unroll
        for (int k = 0; k < HH; k++)
            acc = fmaf(g_pool[b * HH + k] * invN, W1[k * HH + j], acc);
        z[idx] = fmaxf(acc, 0.f);
    }
    __syncthreads();
    for (int idx = tid; idx < NB * NDOUT; idx += 256) {
        int b = idx >> 7, o = idx & 127;
        float acc = b2[o];
#pragma unroll
        for (int j = 0; j < HH; j++)
            acc = fmaf(z[b * HH + j], W2[j * NDOUT + o], acc);
        out[idx] = acc;
    }
}

// ---------------- GEMM1: y = W1^T @ [h ; agg], K=128, fp16 in, cp.async -----
__global__ __launch_bounds__(256) void mma_gemm1(const float* __restrict__ W,
                                                 const float* __restrict__ bias,
                                                 int hsel, int useOut) {
    extern __shared__ char smem[];
    float* bias_s = (float*)smem;
    uint4* Wp = (uint4*)(smem + 1024);                // [4 fq][8 ks16][32] = 16KB
    char* As = smem + 1024 + 16384;                   // 128 rows x RB
    const uint32_t As_u = (uint32_t)__cvta_generic_to_shared(As);

    const int tid = threadIdx.x, lid = tid & 31, wid = tid >> 5;
    const int r = lid >> 2, cq = lid & 3;
    const int mq = wid & 1, nq = wid >> 1;
    const __half* hbase = hsel ? g_h2 : g_h;

    if (tid < 64) bias_s[tid] = bias[tid];
    for (int e = tid; e < 1024; e += 256) {
        int lane = e & 31, ks16 = (e >> 5) & 7, fq = e >> 8;
        int er = lane >> 2, ec = lane & 3;
        int m0 = fq * 16, k0 = ks16 * 16;
        uint4 w;
        w.x = f2h(W[(k0 + 2*ec)     * HH + m0 + er], W[(k0 + 2*ec + 1) * HH + m0 + er]);
        w.y = f2h(W[(k0 + 2*ec)     * HH + m0 + 8 + er], W[(k0 + 2*ec + 1) * HH + m0 + 8 + er]);
        w.z = f2h(W[(k0 + 2*ec + 8) * HH + m0 + er], W[(k0 + 2*ec + 9) * HH + m0 + er]);
        w.w = f2h(W[(k0 + 2*ec + 8) * HH + m0 + 8 + er], W[(k0 + 2*ec + 9) * HH + m0 + 8 + er]);
        Wp[e] = w;
    }

    float st[2][2] = {{0.f, 0.f}, {0.f, 0.f}};
    float sq[2][2] = {{0.f, 0.f}, {0.f, 0.f}};

    // prologue: issue all 4 chunks of tile 0
    {
        int T = blockIdx.x * TPC;
        int b = T >> 8, n0 = (T & 255) << 7;
        for (int c = 0; c < 4; c++) {
#pragma unroll
            for (int i = 0; i < 2; i++) {
                int idx = tid + i * 256;
                int k = c * 32 + (idx >> 4), n8 = idx & 15;
                const __half* src = ((k < HH) ? hbase : g_agg) +
                                    ((size_t)(b * HH + (k & 63))) * NN + n0 + n8 * 8;
                cpa16(As_u + (uint32_t)(k * RB + n8 * 16), src);
            }
            cpcommit();
        }
    }
    __syncthreads();   // RACE FIX (R9/R10 bug): bias_s/Wp fills visible before acc init

    for (int t = 0; t < TPC; t++) {
        int T = blockIdx.x * TPC + t;
        int b = T >> 8, n0 = (T & 255) << 7;

        float acc[2][4][4];
        {
            float b0 = bias_s[mq * 32 + r],       b1v = bias_s[mq * 32 + 8 + r];
            float b2v = bias_s[mq * 32 + 16 + r], b3 = bias_s[mq * 32 + 24 + r];
#pragma unroll
            for (int nt = 0; nt < 4; nt++) {
                acc[0][nt][0] = b0;  acc[0][nt][1] = b0;
                acc[0][nt][2] = b1v; acc[0][nt][3] = b1v;
                acc[1][nt][0] = b2v; acc[1][nt][1] = b2v;
                acc[1][nt][2] = b3;  acc[1][nt][3] = b3;
            }
        }

        for (int c = 0; c < 4; c++) {
            cpwait(3 - c);
            __syncthreads();
#pragma unroll
            for (int j = 0; j < 2; j++) {
                int ks16 = c * 2 + j;
                uint4 A0 = Wp[((mq * 2 + 0) * 8 + ks16) * 32 + lid];
                uint4 A1 = Wp[((mq * 2 + 1) * 8 + ks16) * 32 + lid];
                uint32_t rowa = As_u + (uint32_t)((ks16 * 16 + (lid & 15)) * RB +
                                (nq * 32 + (lid >> 4) * 8) * 2);
                uint32_t b0, b1, b2, b3, b4, b5, b6, b7;
                LDMX4T(b0, b1, b2, b3, rowa);
                LDMX4T(b4, b5, b6, b7, rowa + 32);
                mma_f16(acc[0][0], A0, b0, b1); mma_f16(acc[1][0], A1, b0, b1);
                mma_f16(acc[0][1], A0, b2, b3); mma_f16(acc[1][1], A1, b2, b3);
                mma_f16(acc[0][2], A0, b4, b5); mma_f16(acc[1][2], A1, b4, b5);
                mma_f16(acc[0][3], A0, b6, b7); mma_f16(acc[1][3], A1, b6, b7);
            }
        }
        __syncthreads();

        if (t + 1 < TPC) {
            int T2 = T + 1;
            int b2 = T2 >> 8, n02 = (T2 & 255) << 7;
            for (int c = 0; c < 4; c++) {
#pragma unroll
                for (int i = 0; i < 2; i++) {
                    int idx = tid + i * 256;
                    int k = c * 32 + (idx >> 4), n8 = idx & 15;
                    const __half* src = ((k < HH) ? hbase : g_agg) +
                                        ((size_t)(b2 * HH + (k & 63))) * NN + n02 + n8 * 8;
                    cpa16(As_u + (uint32_t)(k * RB + n8 * 16), src);
                }
                cpcommit();
            }
        }

#pragma unroll
        for (int f = 0; f < 2; f++) {
            size_t base0 = ((size_t)(b * HH + mq * 32 + f * 16 + r)) * NN + n0 + nq * 32;
            size_t base1 = base0 + (size_t)8 * NN;
#pragma unroll
            for (int nt = 0; nt < 4; nt++) {
                int nn = nt * 8 + 2 * cq;
                *(float2*)&g_y[base0 + nn] = make_float2(acc[f][nt][0], acc[f][nt][1]);
                *(float2*)&g_y[base1 + nn] = make_float2(acc[f][nt][2], acc[f][nt][3]);
                st[f][0] += acc[f][nt][0] + acc[f][nt][1];
                sq[f][0] += acc[f][nt][0] * acc[f][nt][0] + acc[f][nt][1] * acc[f][nt][1];
                st[f][1] += acc[f][nt][2] + acc[f][nt][3];
                sq[f][1] += acc[f][nt][2] * acc[f][nt][2] + acc[f][nt][3] * acc[f][nt][3];
            }
        }
    }

#pragma unroll
    for (int d = 1; d < 4; d <<= 1)
#pragma unroll
        for (int f = 0; f < 2; f++)
#pragma unroll
            for (int hv = 0; hv < 2; hv++) {
                st[f][hv] += __shfl_xor_sync(0xffffffffu, st[f][hv], d);
                sq[f][hv] += __shfl_xor_sync(0xffffffffu, sq[f][hv], d);
            }
    if (cq == 0)
#pragma unroll
        for (int f = 0; f < 2; f++) {
            int m = mq * 32 + f * 16 + r;
            atomicAdd(&g_stats[useOut][m], st[f][0]);
            atomicAdd(&g_stats[useOut][HH + m], sq[f][0]);
            atomicAdd(&g_stats[useOut][m + 8], st[f][1]);
            atomicAdd(&g_stats[useOut][HH + m + 8], sq[f][1]);
        }
}

// ---------------- GEMM2: y = W2^T @ relu(bn(y)), K=64, fp32->fp16 smem ------
__global__ __launch_bounds__(256) void mma_gemm2(const float* __restrict__ W,
                                                 const float* __restrict__ bias,
                                                 const float* __restrict__ gamma,
                                                 const float* __restrict__ beta,
                                                 int useIn, int useOut) {
    extern __shared__ char smem[];
    float* bias_s = (float*)smem;
    float* sc_s   = (float*)(smem + 256);
    float* sh_s   = (float*)(smem + 512);
    uint4* Wp = (uint4*)(smem + 1024);                // [4 fq][4 ks16][32] = 8KB
    char* As = smem + 1024 + 8192;                    // 64 rows x RB

    const int tid = threadIdx.x, lid = tid & 31, wid = tid >> 5;
    const int r = lid >> 2, cq = lid & 3;
    const int mq = wid & 1, nq = wid >> 1;
    const uint32_t As_u = (uint32_t)__cvta_generic_to_shared(As);

    if (tid < 64) bias_s[tid] = bias[tid];
    if (tid >= 64 && tid < 128) {
        float sc, sh;
        bn_coef(useIn, tid - 64, gamma, beta, sc, sh);
        sc_s[tid - 64] = sc; sh_s[tid - 64] = sh;
    }
    for (int e = tid; e < 512; e += 256) {
        int lane = e & 31, ks16 = (e >> 5) & 3, fq = e >> 7;
        int er = lane >> 2, ec = lane & 3;
        int m0 = fq * 16, k0 = ks16 * 16;
        uint4 w;
        w.x = f2h(W[(k0 + 2*ec)     * HH + m0 + er], W[(k0 + 2*ec + 1) * HH + m0 + er]);
        w.y = f2h(W[(k0 + 2*ec)     * HH + m0 + 8 + er], W[(k0 + 2*ec + 1) * HH + m0 + 8 + er]);
        w.z = f2h(W[(k0 + 2*ec + 8) * HH + m0 + er], W[(k0 + 2*ec + 9) * HH + m0 + er]);
        w.w = f2h(W[(k0 + 2*ec + 8) * HH + m0 + 8 + er], W[(k0 + 2*ec + 9) * HH + m0 + 8 + er]);
        Wp[e] = w;
    }
    __syncthreads();   // bias_s/sc_s/sh_s/Wp ready

    const int myk = tid >> 5;        // fill decode: k = c*32 + myk + i*8
    const int myc4 = tid & 31;       // node quad

    float st[2][2] = {{0.f, 0.f}, {0.f, 0.f}};
    float sq[2][2] = {{0.f, 0.f}, {0.f, 0.f}};

    float4 pfA[4], pfB[4];
    auto loadc = [&](int t, int c, float4* pf) {
        int T = blockIdx.x * TPC + t;
        int b = T >> 8, n0 = (T & 255) << 7;
#pragma unroll
        for (int i = 0; i < 4; i++) {
            int k = c * 32 + myk + i * 8;
            pf[i] = *(const float4*)(g_y + ((size_t)(b * HH + k)) * NN + n0 + myc4 * 4);
        }
    };
    auto stsc = [&](int c, const float4* pf) {
#pragma unroll
        for (int i = 0; i < 4; i++) {
            int k = c * 32 + myk + i * 8;
            float sc = sc_s[k], sh = sh_s[k];
            float4 v = pf[i];
            uint2 o;
            o.x = f2h(fmaxf(fmaf(v.x, sc, sh), 0.f), fmaxf(fmaf(v.y, sc, sh), 0.f));
            o.y = f2h(fmaxf(fmaf(v.z, sc, sh), 0.f), fmaxf(fmaf(v.w, sc, sh), 0.f));
            *(uint2*)(As + k * RB + myc4 * 8) = o;
        }
    };
    auto mmachunk = [&](int c, float acc[2][4][4]) {
#pragma unroll
        for (int j = 0; j < 2; j++) {
            int ks16 = c * 2 + j;
            uint4 A0 = Wp[((mq * 2 + 0) * 4 + ks16) * 32 + lid];
            uint4 A1 = Wp[((mq * 2 + 1) * 4 + ks16) * 32 + lid];
            uint32_t rowa = As_u + (uint32_t)((ks16 * 16 + (lid & 15)) * RB +
                            (nq * 32 + (lid >> 4) * 8) * 2);
            uint32_t b0, b1, b2, b3, b4, b5, b6, b7;
            LDMX4T(b0, b1, b2, b3, rowa);
            LDMX4T(b4, b5, b6, b7, rowa + 32);
            mma_f16(acc[0][0], A0, b0, b1); mma_f16(acc[1][0], A1, b0, b1);
            mma_f16(acc[0][1], A0, b2, b3); mma_f16(acc[1][1], A1, b2, b3);
            mma_f16(acc[0][2], A0, b4, b5); mma_f16(acc[1][2], A1, b4, b5);
            mma_f16(acc[0][3], A0, b6, b7); mma_f16(acc[1][3], A1, b6, b7);
        }
    };

    loadc(0, 0, pfA);
    for (int t = 0; t < TPC; t++) {
        int T = blockIdx.x * TPC + t;
        int b = T >> 8, n0 = (T & 255) << 7;

        stsc(0, pfA);
        loadc(t, 1, pfB);
        __syncthreads();            // chunk 0 visible

        float acc[2][4][4];
        {
            float b0 = bias_s[mq * 32 + r],       b1v = bias_s[mq * 32 + 8 + r];
            float b2v = bias_s[mq * 32 + 16 + r], b3 = bias_s[mq * 32 + 24 + r];
#pragma unroll
            for (int nt = 0; nt < 4; nt++) {
                acc[0][nt][0] = b0;  acc[0][nt][1] = b0;
                acc[0][nt][2] = b1v; acc[0][nt][3] = b1v;
                acc[1][nt][0] = b2v; acc[1][nt][1] = b2v;
                acc[1][nt][2] = b3;  acc[1][nt][3] = b3;
            }
        }

        mmachunk(0, acc);
        stsc(1, pfB);               // disjoint region: safe during chunk-0 MMAs
        if (t + 1 < TPC) loadc(t + 1, 0, pfA);
        __syncthreads();            // chunk 1 visible + chunk-0 reads done
        mmachunk(1, acc);

#pragma unroll
        for (int f = 0; f < 2; f++) {
            size_t base0 = ((size_t)(b * HH + mq * 32 + f * 16 + r)) * NN + n0 + nq * 32;
            size_t base1 = base0 + (size_t)8 * NN;
#pragma unroll
            for (int nt = 0; nt < 4; nt++) {
                int nn = nt * 8 + 2 * cq;
                *(float2*)&g_y[base0 + nn] = make_float2(acc[f][nt][0], acc[f][nt][1]);
                *(float2*)&g_y[base1 + nn] = make_float2(acc[f][nt][2], acc[f][nt][3]);
                st[f][0] += acc[f][nt][0] + acc[f][nt][1];
                sq[f][0] += acc[f][nt][0] * acc[f][nt][0] + acc[f][nt][1] * acc[f][nt][1];
                st[f][1] += acc[f][nt][2] + acc[f][nt][3];
                sq[f][1] += acc[f][nt][2] * acc[f][nt][2] + acc[f][nt][3] * acc[f][nt][3];
            }
        }
        __syncthreads();            // As reads done before next tile's STS
    }

#pragma unroll
    for (int d = 1; d < 4; d <<= 1)
#pragma unroll
        for (int f = 0; f < 2; f++)
#pragma unroll
            for (int hv = 0; hv < 2; hv++) {
                st[f][hv] += __shfl_xor_sync(0xffffffffu, st[f][hv], d);
                sq[f][hv] += __shfl_xor_sync(0xffffffffu, sq[f][hv], d);
            }
    if (cq == 0)
#pragma unroll
        for (int f = 0; f < 2; f++) {
            int m = mq * 32 + f * 16 + r;
            atomicAdd(&g_stats[useOut][m], st[f][0]);
            atomicAdd(&g_stats[useOut][HH + m], sq[f][0]);
            atomicAdd(&g_stats[useOut][m + 8], st[f][1]);
            atomicAdd(&g_stats[useOut][HH + m + 8], sq[f][1]);
        }
}

// ---------------- driver ---------------------------------------------------
extern "C" void kernel_launch(void* const* d_in, const int* in_sizes, int n_in,
                              void* d_out, int out_size) {
    const float* x    = (const float*)d_in[0];
    const float* embW = (const float*)d_in[2];
    const float* embB = (const float*)d_in[3];
    const float* W1   = (const float*)d_in[4];
    const float* b1   = (const float*)d_in[5];
    const float* g1   = (const float*)d_in[6];
    const float* be1  = (const float*)d_in[7];
    const float* W2   = (const float*)d_in[8];
    const float* b2   = (const float*)d_in[9];
    const float* g2   = (const float*)d_in[10];
    const float* be2  = (const float*)d_in[11];
    const float* hW1  = (const float*)d_in[12];
    const float* hb1  = (const float*)d_in[13];
    const float* hW2  = (const float*)d_in[14];
    const float* hb2  = (const float*)d_in[15];
    float* out = (float*)d_out;

    const int SMEM_G1 = 1024 + 16384 + 128 * RB;  // 52224
    const int SMEM_G2 = 1024 + 8192 + 64 * RB;    // 26624
    cudaFuncSetAttribute(mma_gemm1, cudaFuncAttributeMaxDynamicSharedMemorySize, SMEM_G1);
    cudaFuncSetAttribute(mma_gemm2, cudaFuncAttributeMaxDynamicSharedMemorySize, SMEM_G2);

    const int GRID = MROWS / 128 / TPC;  // 1024

    zero_kernel<<<1, 256>>>();
    embed_kernel<<<dim3(16, HH, NB), 256>>>(x, embW, embB);
    agg_kernel<<<dim3(16, HH, NB), 256>>>();
    for (int l = 0; l < 3; l++) {
        int hsel = l & 1;  // l0: g_h, l1: g_h2, l2: g_h
        mma_gemm1<<<GRID, 256, SMEM_G1>>>(W1 + l * 2 * HH * HH, b1 + l * HH, hsel, l * 2);
        mma_gemm2<<<GRID, 256, SMEM_G2>>>(W2 + l * HH * HH, b2 + l * HH,
                                          g1 + l * HH, be1 + l * HH, l * 2, l * 2 + 1);
        if (l < 2)
            fused_res_agg<<<dim3(4, HH, NB), 256>>>(hsel, g2 + l * HH, be2 + l * HH,
                                                    l * 2 + 1);
        else
            relu_pool<<<dim3(4, HH, NB), 256>>>(hsel, g2 + l * HH, be2 + l * HH,
                                                l * 2 + 1);
    }
    head_kernel<<<1, 256>>>(hW1, hb1, hW2, hb2, out);
}

// round 13
// speedup vs baseline: 3.2240x; 1.1373x over previous
#include <cuda_runtime.h>
#include <cuda_fp16.h>
#include <cstdint>

#define NB 16
#define NN 32768          // nodes = 128*256 torus
#define HH 64
#define NDOUT 128
#define MROWS (NB*NN)     // 524288
#define EPSBN 1e-5f
#define RB 272            // As row bytes: 256 data + 16 pad -> conflict-free ldmatrix
#define TPC 4

// ---------------- scratch (feature-major layout: [b][f][n]) ----------------
__device__ __half g_h[NB*HH*NN];     // trunk ping
__device__ __half g_h2[NB*HH*NN];    // trunk pong
__device__ __half g_agg[NB*HH*NN];   // stencil aggregate (gemm1 input)
__device__ __half g_y[NB*HH*NN];     // gemm outputs (pre-BN), fp16; stats from fp32 accs
__device__ float  g_stats[6][2*HH];
__device__ float  g_pool[NB*HH];

// ---------------- helpers ---------------------------------------------------
__device__ __forceinline__ float2 h2f(uint32_t u) {
    __half2 h = *(__half2*)&u;
    return __half22float2(h);
}
__device__ __forceinline__ uint32_t f2h(float a, float b) {
    __half2 h = __floats2half2_rn(a, b);
    return *(uint32_t*)&h;
}
__device__ __forceinline__ void u4tof8(uint4 u, float* f) {
    float2 a = h2f(u.x), b = h2f(u.y), c = h2f(u.z), d = h2f(u.w);
    f[0] = a.x; f[1] = a.y; f[2] = b.x; f[3] = b.y;
    f[4] = c.x; f[5] = c.y; f[6] = d.x; f[7] = d.y;
}
__device__ __forceinline__ uint4 f8tou4(const float* f) {
    uint4 u;
    u.x = f2h(f[0], f[1]); u.y = f2h(f[2], f[3]);
    u.z = f2h(f[4], f[5]); u.w = f2h(f[6], f[7]);
    return u;
}
__device__ __forceinline__ void mma_f16(float* d, const uint4& a, uint32_t b0, uint32_t b1) {
    asm volatile(
        "mma.sync.aligned.m16n8k16.row.col.f32.f16.f16.f32 "
        "{%0,%1,%2,%3}, {%4,%5,%6,%7}, {%8,%9}, {%0,%1,%2,%3};"
        : "+f"(d[0]), "+f"(d[1]), "+f"(d[2]), "+f"(d[3])
        : "r"(a.x), "r"(a.y), "r"(a.z), "r"(a.w), "r"(b0), "r"(b1));
}
#define LDMX4T(r0, r1, r2, r3, addr) \
    asm volatile("ldmatrix.sync.aligned.m8n8.x4.trans.shared.b16 {%0,%1,%2,%3}, [%4];" \
        : "=r"(r0), "=r"(r1), "=r"(r2), "=r"(r3) : "r"(addr))
__device__ __forceinline__ void bn_coef(int use, int f, const float* g, const float* be,
                                        float& sc, float& sh) {
    const float invM = 1.f / (float)MROWS;
    float s = g_stats[use][f], q = g_stats[use][HH + f];
    float m = s * invM;
    float v = q * invM - m * m;
    float r = rsqrtf(v + EPSBN);
    sc = g[f] * r;
    sh = fmaf(-m, sc, be[f]);
}
__device__ __forceinline__ void cpa16(uint32_t dst, const void* src) {
    asm volatile("cp.async.cg.shared.global [%0], [%1], 16;" :: "r"(dst), "l"(src));
}
__device__ __forceinline__ void cpcommit() { asm volatile("cp.async.commit_group;"); }
__device__ __forceinline__ void cpwait(int n) {
    switch (n) {
        case 0: asm volatile("cp.async.wait_group 0;"); break;
        case 1: asm volatile("cp.async.wait_group 1;"); break;
        case 2: asm volatile("cp.async.wait_group 2;"); break;
        default: asm volatile("cp.async.wait_group 3;"); break;
    }
}

// ---------------- small kernels ---------------------------------------------
__global__ void zero_kernel() {
    int tid = threadIdx.x;
    float* s = &g_stats[0][0];
    for (int i = tid; i < 6 * 2 * HH; i += 256) s[i] = 0.f;
    for (int i = tid; i < NB * HH; i += 256) g_pool[i] = 0.f;
}

// h[b][f][n] = relu(sum_c x[b][c][n] W[c][f] + b[f]) -> fp16
__global__ void embed_kernel(const float* __restrict__ x,
                             const float* __restrict__ W,
                             const float* __restrict__ bias) {
    int b = blockIdx.z, f = blockIdx.y;
    float w0 = W[f], w1 = W[HH + f], w2 = W[2 * HH + f], bb = bias[f];
    int n = blockIdx.x * 2048 + threadIdx.x * 8;
    const float* xb = x + (size_t)(b * 3) * NN + n;
    float r[8];
#pragma unroll
    for (int h = 0; h < 2; h++) {
        float4 a = *(const float4*)(xb + h * 4);
        float4 c = *(const float4*)(xb + NN + h * 4);
        float4 d = *(const float4*)(xb + 2 * NN + h * 4);
        r[h*4+0] = fmaxf(fmaf(a.x, w0, fmaf(c.x, w1, fmaf(d.x, w2, bb))), 0.f);
        r[h*4+1] = fmaxf(fmaf(a.y, w0, fmaf(c.y, w1, fmaf(d.y, w2, bb))), 0.f);
        r[h*4+2] = fmaxf(fmaf(a.z, w0, fmaf(c.z, w1, fmaf(d.z, w2, bb))), 0.f);
        r[h*4+3] = fmaxf(fmaf(a.w, w0, fmaf(c.w, w1, fmaf(d.w, w2, bb))), 0.f);
    }
    *(uint4*)(g_h + (size_t)(b * HH + f) * NN + n) = f8tou4(r);
}

// initial aggregate from g_h (layer 0)
__global__ void agg_kernel() {
    int b = blockIdx.z, f = blockIdx.y;
    const __half* hp = g_h + (size_t)(b * HH + f) * NN;
    int n = blockIdx.x * 2048 + threadIdx.x * 8;
    uint4 u8 = *(const uint4*)(hp + ((n + 256) & 32767));
    uint4 d8 = *(const uint4*)(hp + ((n - 256) & 32767));
    uint4 c8 = *(const uint4*)(hp + n);
    float lf = __half2float(hp[((n & 255) == 0) ? n + 255 : n - 1]);
    float rt = __half2float(hp[(((n + 7) & 255) == 255) ? n - 248 : n + 8]);
    float u[8], d[8], c[8], o[8];
    u4tof8(u8, u); u4tof8(d8, d); u4tof8(c8, c);
#pragma unroll
    for (int j = 0; j < 8; j++) {
        float L = (j == 0) ? lf : c[j - 1];
        float R = (j == 7) ? rt : c[j + 1];
        o[j] = 0.25f * (u[j] + d[j] + L + R);
    }
    *(uint4*)(g_agg + (size_t)(b * HH + f) * NN + n) = f8tou4(o);
}

// ---------------- fused: h_out = h_in + relu(bn(y)); agg = stencil(h_out) ---
__global__ __launch_bounds__(256) void fused_res_agg(int hselIn,
                                                     const float* __restrict__ gamma,
                                                     const float* __restrict__ beta,
                                                     int use) {
    __shared__ float hb[8704];
    __shared__ float ss[2];
    int b = blockIdx.z, f = blockIdx.y, tid = threadIdx.x;
    if (tid == 0) {
        float sc, sh;
        bn_coef(use, f, gamma, beta, sc, sh);
        ss[0] = sc; ss[1] = sh;
    }
    __syncthreads();
    float sc = ss[0], sh = ss[1];
    const __half* hin = hselIn ? g_h2 : g_h;
    __half* hout = hselIn ? g_h : g_h2;
    size_t plane = (size_t)(b * HH + f) * NN;
    int n0 = blockIdx.x * 8192;

    for (int q8 = tid; q8 < 1088; q8 += 256) {
        int nh = (n0 - 256 + q8 * 8) & 32767;
        float hf[8], yf[8];
        u4tof8(*(const uint4*)(hin + plane + nh), hf);
        u4tof8(*(const uint4*)(g_y + plane + nh), yf);
#pragma unroll
        for (int j = 0; j < 8; j++) hf[j] += fmaxf(fmaf(yf[j], sc, sh), 0.f);
        *(float4*)&hb[q8 * 8] = make_float4(hf[0], hf[1], hf[2], hf[3]);
        *(float4*)&hb[q8 * 8 + 4] = make_float4(hf[4], hf[5], hf[6], hf[7]);
        if (q8 >= 32 && q8 < 1056) *(uint4*)(hout + plane + nh) = f8tou4(hf);
    }
    __syncthreads();
    for (int q8 = tid; q8 < 1024; q8 += 256) {
        int i = 256 + q8 * 8;
        int n = n0 + q8 * 8;
        float o[8];
#pragma unroll
        for (int j = 0; j < 8; j++) {
            int zj = (n + j) & 255;
            int rowbase = i + j - zj;
            float lf = hb[rowbase + ((zj + 255) & 255)];
            float rt = hb[rowbase + ((zj + 1) & 255)];
            o[j] = 0.25f * (hb[i + j - 256] + hb[i + j + 256] + lf + rt);
        }
        *(uint4*)(g_agg + plane + n) = f8tou4(o);
    }
}

// ---------------- final layer: pool(h_in + relu(bn(y))), no h write ---------
__global__ __launch_bounds__(256) void relu_pool(int hselIn,
                                                 const float* __restrict__ gamma,
                                                 const float* __restrict__ beta,
                                                 int use) {
    __shared__ float ss[2];
    __shared__ float wsum[8];
    int b = blockIdx.z, f = blockIdx.y, tid = threadIdx.x;
    if (tid == 0) {
        float sc, sh;
        bn_coef(use, f, gamma, beta, sc, sh);
        ss[0] = sc; ss[1] = sh;
    }
    __syncthreads();
    float sc = ss[0], sh = ss[1];
    const __half* hin = hselIn ? g_h2 : g_h;
    size_t plane = (size_t)(b * HH + f) * NN;
    int n0 = blockIdx.x * 8192;
    float ps = 0.f;
    for (int q8 = tid; q8 < 1024; q8 += 256) {
        int n = n0 + q8 * 8;
        float hf[8], yf[8];
        u4tof8(*(const uint4*)(hin + plane + n), hf);
        u4tof8(*(const uint4*)(g_y + plane + n), yf);
#pragma unroll
        for (int j = 0; j < 8; j++) ps += hf[j] + fmaxf(fmaf(yf[j], sc, sh), 0.f);
    }
#pragma unroll
    for (int off = 16; off; off >>= 1) ps += __shfl_down_sync(0xffffffffu, ps, off);
    if ((tid & 31) == 0) wsum[tid >> 5] = ps;
    __syncthreads();
    if (tid == 0) {
        float t = 0.f;
#pragma unroll
        for (int w = 0; w < 8; w++) t += wsum[w];
        atomicAdd(&g_pool[b * HH + f], t);
    }
}

__global__ void head_kernel(const float* __restrict__ W1, const float* __restrict__ b1,
                            const float* __restrict__ W2, const float* __restrict__ b2,
                            float* __restrict__ out) {
    __shared__ float z[NB * HH];
    int tid = threadIdx.x;
    const float invN = 1.f / (float)NN;
    for (int idx = tid; idx < NB * HH; idx += 256) {
        int b = idx >> 6, j = idx & 63;
        float acc = b1[j];
#pragma unroll
        for (int k = 0; k < HH; k++)
            acc = fmaf(g_pool[b * HH + k] * invN, W1[k * HH + j], acc);
        z[idx] = fmaxf(acc, 0.f);
    }
    __syncthreads();
    for (int idx = tid; idx < NB * NDOUT; idx += 256) {
        int b = idx >> 7, o = idx & 127;
        float acc = b2[o];
#pragma unroll
        for (int j = 0; j < HH; j++)
            acc = fmaf(z[b * HH + j], W2[j * NDOUT + o], acc);
        out[idx] = acc;
    }
}

// ---------------- GEMM1: y = W1^T @ [h ; agg], K=128, fp16, cp.async --------
__global__ __launch_bounds__(256) void mma_gemm1(const float* __restrict__ W,
                                                 const float* __restrict__ bias,
                                                 int hsel, int useOut) {
    extern __shared__ char smem[];
    float* bias_s = (float*)smem;
    uint4* Wp = (uint4*)(smem + 1024);                // [4 fq][8 ks16][32] = 16KB
    char* As = smem + 1024 + 16384;                   // 128 rows x RB
    const uint32_t As_u = (uint32_t)__cvta_generic_to_shared(As);

    const int tid = threadIdx.x, lid = tid & 31, wid = tid >> 5;
    const int r = lid >> 2, cq = lid & 3;
    const int mq = wid & 1, nq = wid >> 1;
    const __half* hbase = hsel ? g_h2 : g_h;

    if (tid < 64) bias_s[tid] = bias[tid];
    for (int e = tid; e < 1024; e += 256) {
        int lane = e & 31, ks16 = (e >> 5) & 7, fq = e >> 8;
        int er = lane >> 2, ec = lane & 3;
        int m0 = fq * 16, k0 = ks16 * 16;
        uint4 w;
        w.x = f2h(W[(k0 + 2*ec)     * HH + m0 + er], W[(k0 + 2*ec + 1) * HH + m0 + er]);
        w.y = f2h(W[(k0 + 2*ec)     * HH + m0 + 8 + er], W[(k0 + 2*ec + 1) * HH + m0 + 8 + er]);
        w.z = f2h(W[(k0 + 2*ec + 8) * HH + m0 + er], W[(k0 + 2*ec + 9) * HH + m0 + er]);
        w.w = f2h(W[(k0 + 2*ec + 8) * HH + m0 + 8 + er], W[(k0 + 2*ec + 9) * HH + m0 + 8 + er]);
        Wp[e] = w;
    }

    float st[2][2] = {{0.f, 0.f}, {0.f, 0.f}};
    float sq[2][2] = {{0.f, 0.f}, {0.f, 0.f}};

    // prologue: issue all 4 chunks of tile 0
    {
        int T = blockIdx.x * TPC;
        int b = T >> 8, n0 = (T & 255) << 7;
        for (int c = 0; c < 4; c++) {
#pragma unroll
            for (int i = 0; i < 2; i++) {
                int idx = tid + i * 256;
                int k = c * 32 + (idx >> 4), n8 = idx & 15;
                const __half* src = ((k < HH) ? hbase : g_agg) +
                                    ((size_t)(b * HH + (k & 63))) * NN + n0 + n8 * 8;
                cpa16(As_u + (uint32_t)(k * RB + n8 * 16), src);
            }
            cpcommit();
        }
    }
    __syncthreads();   // bias_s/Wp fills visible before acc init (R9/R10 race fix)

    for (int t = 0; t < TPC; t++) {
        int T = blockIdx.x * TPC + t;
        int b = T >> 8, n0 = (T & 255) << 7;

        float acc[2][4][4];
        {
            float b0 = bias_s[mq * 32 + r],       b1v = bias_s[mq * 32 + 8 + r];
            float b2v = bias_s[mq * 32 + 16 + r], b3 = bias_s[mq * 32 + 24 + r];
#pragma unroll
            for (int nt = 0; nt < 4; nt++) {
                acc[0][nt][0] = b0;  acc[0][nt][1] = b0;
                acc[0][nt][2] = b1v; acc[0][nt][3] = b1v;
                acc[1][nt][0] = b2v; acc[1][nt][1] = b2v;
                acc[1][nt][2] = b3;  acc[1][nt][3] = b3;
            }
        }

        for (int c = 0; c < 4; c++) {
            cpwait(3 - c);
            __syncthreads();
#pragma unroll
            for (int j = 0; j < 2; j++) {
                int ks16 = c * 2 + j;
                uint4 A0 = Wp[((mq * 2 + 0) * 8 + ks16) * 32 + lid];
                uint4 A1 = Wp[((mq * 2 + 1) * 8 + ks16) * 32 + lid];
                uint32_t rowa = As_u + (uint32_t)((ks16 * 16 + (lid & 15)) * RB +
                                (nq * 32 + (lid >> 4) * 8) * 2);
                uint32_t b0, b1, b2, b3, b4, b5, b6, b7;
                LDMX4T(b0, b1, b2, b3, rowa);
                LDMX4T(b4, b5, b6, b7, rowa + 32);
                mma_f16(acc[0][0], A0, b0, b1); mma_f16(acc[1][0], A1, b0, b1);
                mma_f16(acc[0][1], A0, b2, b3); mma_f16(acc[1][1], A1, b2, b3);
                mma_f16(acc[0][2], A0, b4, b5); mma_f16(acc[1][2], A1, b4, b5);
                mma_f16(acc[0][3], A0, b6, b7); mma_f16(acc[1][3], A1, b6, b7);
            }
        }
        __syncthreads();

        if (t + 1 < TPC) {
            int T2 = T + 1;
            int b2 = T2 >> 8, n02 = (T2 & 255) << 7;
            for (int c = 0; c < 4; c++) {
#pragma unroll
                for (int i = 0; i < 2; i++) {
                    int idx = tid + i * 256;
                    int k = c * 32 + (idx >> 4), n8 = idx & 15;
                    const __half* src = ((k < HH) ? hbase : g_agg) +
                                        ((size_t)(b2 * HH + (k & 63))) * NN + n02 + n8 * 8;
                    cpa16(As_u + (uint32_t)(k * RB + n8 * 16), src);
                }
                cpcommit();
            }
        }

#pragma unroll
        for (int f = 0; f < 2; f++) {
            size_t base0 = ((size_t)(b * HH + mq * 32 + f * 16 + r)) * NN + n0 + nq * 32;
            size_t base1 = base0 + (size_t)8 * NN;
#pragma unroll
            for (int nt = 0; nt < 4; nt++) {
                int nn = nt * 8 + 2 * cq;
                *(uint32_t*)(g_y + base0 + nn) = f2h(acc[f][nt][0], acc[f][nt][1]);
                *(uint32_t*)(g_y + base1 + nn) = f2h(acc[f][nt][2], acc[f][nt][3]);
                st[f][0] += acc[f][nt][0] + acc[f][nt][1];
                sq[f][0] += acc[f][nt][0] * acc[f][nt][0] + acc[f][nt][1] * acc[f][nt][1];
                st[f][1] += acc[f][nt][2] + acc[f][nt][3];
                sq[f][1] += acc[f][nt][2] * acc[f][nt][2] + acc[f][nt][3] * acc[f][nt][3];
            }
        }
    }

#pragma unroll
    for (int d = 1; d < 4; d <<= 1)
#pragma unroll
        for (int f = 0; f < 2; f++)
#pragma unroll
            for (int hv = 0; hv < 2; hv++) {
                st[f][hv] += __shfl_xor_sync(0xffffffffu, st[f][hv], d);
                sq[f][hv] += __shfl_xor_sync(0xffffffffu, sq[f][hv], d);
            }
    if (cq == 0)
#pragma unroll
        for (int f = 0; f < 2; f++) {
            int m = mq * 32 + f * 16 + r;
            atomicAdd(&g_stats[useOut][m], st[f][0]);
            atomicAdd(&g_stats[useOut][HH + m], sq[f][0]);
            atomicAdd(&g_stats[useOut][m + 8], st[f][1]);
            atomicAdd(&g_stats[useOut][HH + m + 8], sq[f][1]);
        }
}

// ---------------- GEMM2: y = W2^T @ relu(bn(y)), K=64, fp16, reg-pipelined --
__global__ __launch_bounds__(256) void mma_gemm2(const float* __restrict__ W,
                                                 const float* __restrict__ bias,
                                                 const float* __restrict__ gamma,
                                                 const float* __restrict__ beta,
                                                 int useIn, int useOut) {
    extern __shared__ char smem[];
    float* bias_s = (float*)smem;
    float* sc_s   = (float*)(smem + 256);
    float* sh_s   = (float*)(smem + 512);
    uint4* Wp = (uint4*)(smem + 1024);                // [4 fq][4 ks16][32] = 8KB
    char* As = smem + 1024 + 8192;                    // 64 rows x RB

    const int tid = threadIdx.x, lid = tid & 31, wid = tid >> 5;
    const int r = lid >> 2, cq = lid & 3;
    const int mq = wid & 1, nq = wid >> 1;
    const uint32_t As_u = (uint32_t)__cvta_generic_to_shared(As);

    if (tid < 64) bias_s[tid] = bias[tid];
    if (tid >= 64 && tid < 128) {
        float sc, sh;
        bn_coef(useIn, tid - 64, gamma, beta, sc, sh);
        sc_s[tid - 64] = sc; sh_s[tid - 64] = sh;
    }
    for (int e = tid; e < 512; e += 256) {
        int lane = e & 31, ks16 = (e >> 5) & 3, fq = e >> 7;
        int er = lane >> 2, ec = lane & 3;
        int m0 = fq * 16, k0 = ks16 * 16;
        uint4 w;
        w.x = f2h(W[(k0 + 2*ec)     * HH + m0 + er], W[(k0 + 2*ec + 1) * HH + m0 + er]);
        w.y = f2h(W[(k0 + 2*ec)     * HH + m0 + 8 + er], W[(k0 + 2*ec + 1) * HH + m0 + 8 + er]);
        w.z = f2h(W[(k0 + 2*ec + 8) * HH + m0 + er], W[(k0 + 2*ec + 9) * HH + m0 + er]);
        w.w = f2h(W[(k0 + 2*ec + 8) * HH + m0 + 8 + er], W[(k0 + 2*ec + 9) * HH + m0 + 8 + er]);
        Wp[e] = w;
    }
    __syncthreads();   // bias_s/sc_s/sh_s/Wp ready

    float st[2][2] = {{0.f, 0.f}, {0.f, 0.f}};
    float sq[2][2] = {{0.f, 0.f}, {0.f, 0.f}};

    uint4 pfA[2], pfB[2];
    auto loadc = [&](int t, int c, uint4* pf) {
        int T = blockIdx.x * TPC + t;
        int b = T >> 8, n0 = (T & 255) << 7;
#pragma unroll
        for (int i = 0; i < 2; i++) {
            int idx = tid + i * 256;
            int k = c * 32 + (idx >> 4), n8 = idx & 15;
            pf[i] = *(const uint4*)(g_y + ((size_t)(b * HH + k)) * NN + n0 + n8 * 8);
        }
    };
    auto stsc = [&](int c, const uint4* pf) {
#pragma unroll
        for (int i = 0; i < 2; i++) {
            int idx = tid + i * 256;
            int k = c * 32 + (idx >> 4), n8 = idx & 15;
            float sc = sc_s[k], sh = sh_s[k];
            float v[8];
            u4tof8(pf[i], v);
#pragma unroll
            for (int j = 0; j < 8; j++) v[j] = fmaxf(fmaf(v[j], sc, sh), 0.f);
            *(uint4*)(As + k * RB + n8 * 16) = f8tou4(v);
        }
    };
    auto mmachunk = [&](int c, float acc[2][4][4]) {
#pragma unroll
        for (int j = 0; j < 2; j++) {
            int ks16 = c * 2 + j;
            uint4 A0 = Wp[((mq * 2 + 0) * 4 + ks16) * 32 + lid];
            uint4 A1 = Wp[((mq * 2 + 1) * 4 + ks16) * 32 + lid];
            uint32_t rowa = As_u + (uint32_t)((ks16 * 16 + (lid & 15)) * RB +
                            (nq * 32 + (lid >> 4) * 8) * 2);
            uint32_t b0, b1, b2, b3, b4, b5, b6, b7;
            LDMX4T(b0, b1, b2, b3, rowa);
            LDMX4T(b4, b5, b6, b7, rowa + 32);
            mma_f16(acc[0][0], A0, b0, b1); mma_f16(acc[1][0], A1, b0, b1);
            mma_f16(acc[0][1], A0, b2, b3); mma_f16(acc[1][1], A1, b2, b3);
            mma_f16(acc[0][2], A0, b4, b5); mma_f16(acc[1][2], A1, b4, b5);
            mma_f16(acc[0][3], A0, b6, b7); mma_f16(acc[1][3], A1, b6, b7);
        }
    };

    loadc(0, 0, pfA);
    for (int t = 0; t < TPC; t++) {
        int T = blockIdx.x * TPC + t;
        int b = T >> 8, n0 = (T & 255) << 7;

        stsc(0, pfA);
        loadc(t, 1, pfB);
        __syncthreads();            // chunk 0 visible

        float acc[2][4][4];
        {
            float b0 = bias_s[mq * 32 + r],       b1v = bias_s[mq * 32 + 8 + r];
            float b2v = bias_s[mq * 32 + 16 + r], b3 = bias_s[mq * 32 + 24 + r];
#pragma unroll
            for (int nt = 0; nt < 4; nt++) {
                acc[0][nt][0] = b0;  acc[0][nt][1] = b0;
                acc[0][nt][2] = b1v; acc[0][nt][3] = b1v;
                acc[1][nt][0] = b2v; acc[1][nt][1] = b2v;
                acc[1][nt][2] = b3;  acc[1][nt][3] = b3;
            }
        }

        mmachunk(0, acc);
        stsc(1, pfB);               // disjoint region: safe during chunk-0 MMAs
        if (t + 1 < TPC) loadc(t + 1, 0, pfA);
        __syncthreads();            // chunk 1 visible + chunk-0 reads done
        mmachunk(1, acc);

#pragma unroll
        for (int f = 0; f < 2; f++) {
            size_t base0 = ((size_t)(b * HH + mq * 32 + f * 16 + r)) * NN + n0 + nq * 32;
            size_t base1 = base0 + (size_t)8 * NN;
#pragma unroll
            for (int nt = 0; nt < 4; nt++) {
                int nn = nt * 8 + 2 * cq;
                *(uint32_t*)(g_y + base0 + nn) = f2h(acc[f][nt][0], acc[f][nt][1]);
                *(uint32_t*)(g_y + base1 + nn) = f2h(acc[f][nt][2], acc[f][nt][3]);
                st[f][0] += acc[f][nt][0] + acc[f][nt][1];
                sq[f][0] += acc[f][nt][0] * acc[f][nt][0] + acc[f][nt][1] * acc[f][nt][1];
                st[f][1] += acc[f][nt][2] + acc[f][nt][3];
                sq[f][1] += acc[f][nt][2] * acc[f][nt][2] + acc[f][nt][3] * acc[f][nt][3];
            }
        }
        __syncthreads();            // As reads done before next tile's STS
    }

#pragma unroll
    for (int d = 1; d < 4; d <<= 1)
#pragma unroll
        for (int f = 0; f < 2; f++)
#pragma unroll
            for (int hv = 0; hv < 2; hv++) {
                st[f][hv] += __shfl_xor_sync(0xffffffffu, st[f][hv], d);
                sq[f][hv] += __shfl_xor_sync(0xffffffffu, sq[f][hv], d);
            }
    if (cq == 0)
#pragma unroll
        for (int f = 0; f < 2; f++) {
            int m = mq * 32 + f * 16 + r;
            atomicAdd(&g_stats[useOut][m], st[f][0]);
            atomicAdd(&g_stats[useOut][HH + m], sq[f][0]);
            atomicAdd(&g_stats[useOut][m + 8], st[f][1]);
            atomicAdd(&g_stats[useOut][HH + m + 8], sq[f][1]);
        }
}

// ---------------- driver ---------------------------------------------------
extern "C" void kernel_launch(void* const* d_in, const int* in_sizes, int n_in,
                              void* d_out, int out_size) {
    const float* x    = (const float*)d_in[0];
    const float* embW = (const float*)d_in[2];
    const float* embB = (const float*)d_in[3];
    const float* W1   = (const float*)d_in[4];
    const float* b1   = (const float*)d_in[5];
    const float* g1   = (const float*)d_in[6];
    const float* be1  = (const float*)d_in[7];
    const float* W2   = (const float*)d_in[8];
    const float* b2   = (const float*)d_in[9];
    const float* g2   = (const float*)d_in[10];
    const float* be2  = (const float*)d_in[11];
    const float* hW1  = (const float*)d_in[12];
    const float* hb1  = (const float*)d_in[13];
    const float* hW2  = (const float*)d_in[14];
    const float* hb2  = (const float*)d_in[15];
    float* out = (float*)d_out;

    const int SMEM_G1 = 1024 + 16384 + 128 * RB;  // 52224
    const int SMEM_G2 = 1024 + 8192 + 64 * RB;    // 26624
    cudaFuncSetAttribute(mma_gemm1, cudaFuncAttributeMaxDynamicSharedMemorySize, SMEM_G1);
    cudaFuncSetAttribute(mma_gemm2, cudaFuncAttributeMaxDynamicSharedMemorySize, SMEM_G2);

    const int GRID = MROWS / 128 / TPC;  // 1024

    zero_kernel<<<1, 256>>>();
    embed_kernel<<<dim3(16, HH, NB), 256>>>(x, embW, embB);
    agg_kernel<<<dim3(16, HH, NB), 256>>>();
    for (int l = 0; l < 3; l++) {
        int hsel = l & 1;  // l0: g_h, l1: g_h2, l2: g_h
        mma_gemm1<<<GRID, 256, SMEM_G1>>>(W1 + l * 2 * HH * HH, b1 + l * HH, hsel, l * 2);
        mma_gemm2<<<GRID, 256, SMEM_G2>>>(W2 + l * HH * HH, b2 + l * HH,
                                          g1 + l * HH, be1 + l * HH, l * 2, l * 2 + 1);
        if (l < 2)
            fused_res_agg<<<dim3(4, HH, NB), 256>>>(hsel, g2 + l * HH, be2 + l * HH,
                                                    l * 2 + 1);
        else
            relu_pool<<<dim3(4, HH, NB), 256>>>(hsel, g2 + l * HH, be2 + l * HH,
                                                l * 2 + 1);
    }
    head_kernel<<<1, 256>>>(hW1, hb1, hW2, hb2, out);
}